// round 11
// baseline (speedup 1.0000x reference)
#include <cuda_runtime.h>
#include <cstdint>

#define HWSZ 268324
#define HW4  67081
#define WD 518
#define ROWP 520
#define NIMG 64
#define CAP 32768
#define SLOTS 12
#define EPSV 1e-8
#define SAMPN 8192
#define SSTRIDE 8385
#define BANDSZ 7252        // 14 rows * 518
#define NBANDS 37
#define NTILES (NBANDS * NIMG)   // 2368
#define MAINGRID 592             // 2368 / 4
#define L1W 259
#define L1SZ (259*259)
#define G8 33540           // full 8-element groups per image

// ---------------- static device scratch ----------------
__device__ int g_mmode;
__device__ float g_vlo[128], g_vhi[128];
__device__ int g_flag[128];
__device__ unsigned g_cnt[NIMG];
__device__ unsigned g_done[NIMG];
__device__ unsigned g_nb[128];
__device__ double g_sb[128];
__device__ double g_stot[128];
__device__ unsigned g_ccnt[128];
__device__ float g_cand[128][CAP];
__device__ float g_med[128], g_isc[128];
__device__ double g_rho[NIMG];
__device__ double g_gx[4], g_gy[4];
__device__ unsigned long long g_cx[4], g_cy[4];

__device__ float d1buf[NIMG * L1SZ];
__device__ unsigned char m1buf[NIMG * L1SZ];
__device__ float d2buf[NIMG * 129 * 129];
__device__ unsigned char m2buf[NIMG * 129 * 129];

// ---------------- helpers ----------------
__device__ __forceinline__ unsigned monot(float x) {
    unsigned u = __float_as_uint(x);
    return (u >> 31) ? ~u : (u | 0x80000000u);
}
__device__ __forceinline__ float inv_monot(unsigned k) {
    unsigned u = (k >> 31) ? (k & 0x7FFFFFFFu) : ~k;
    return __uint_as_float(u);
}
__device__ __forceinline__ bool maskRT(const void* m, int i, int mode) {
    return (mode == 0) ? ((const unsigned char*)m)[i] != 0
         : (mode == 2) ? ((const int*)m)[i] != 0
         : ((const float*)m)[i] != 0.f;
}

template <int MODE>
__device__ __forceinline__ bool maskAt(const void* m, int i) {
    if (MODE == 0) return ((const unsigned char*)m)[i] != 0;
    if (MODE == 2) return ((const int*)m)[i] != 0;
    return ((const float*)m)[i] != 0.f;
}
template <int MODE>
__device__ __forceinline__ void loadMask4(const void* m, int g4, bool& b0, bool& b1, bool& b2, bool& b3) {
    if (MODE == 0) { uchar4 v = ((const uchar4*)m)[g4]; b0 = v.x; b1 = v.y; b2 = v.z; b3 = v.w; }
    else if (MODE == 2) { int4 v = ((const int4*)m)[g4]; b0 = v.x != 0; b1 = v.y != 0; b2 = v.z != 0; b3 = v.w != 0; }
    else { float4 v = ((const float4*)m)[g4]; b0 = v.x != 0.f; b1 = v.y != 0.f; b2 = v.z != 0.f; b3 = v.w != 0.f; }
}
template <int MODE>
__device__ __forceinline__ void loadMask2(const void* m, int g2, bool& b0, bool& b1) {
    if (MODE == 0) { uchar2 v = ((const uchar2*)m)[g2]; b0 = v.x; b1 = v.y; }
    else if (MODE == 2) { int2 v = ((const int2*)m)[g2]; b0 = v.x != 0; b1 = v.y != 0; }
    else { float2 v = ((const float2*)m)[g2]; b0 = v.x != 0.f; b1 = v.y != 0.f; }
}

template <int NT>
__device__ __forceinline__ double blockReduceD(double v, double* sh) {
    constexpr int NW = NT / 32;
    for (int o = 16; o; o >>= 1) v += __shfl_down_sync(0xffffffffu, v, o);
    int w = threadIdx.x >> 5, l = threadIdx.x & 31;
    if (l == 0) sh[w] = v;
    __syncthreads();
    double r = 0;
    if (threadIdx.x < NW) {
        r = sh[threadIdx.x];
        for (int o = NW / 2; o; o >>= 1) r += __shfl_down_sync((unsigned)((1ull << NW) - 1), r, o);
    }
    return r;
}
template <int NT>
__device__ __forceinline__ unsigned long long blockReduceU(unsigned long long v, unsigned long long* sh) {
    constexpr int NW = NT / 32;
    for (int o = 16; o; o >>= 1) v += __shfl_down_sync(0xffffffffu, v, o);
    int w = threadIdx.x >> 5, l = threadIdx.x & 31;
    if (l == 0) sh[w] = v;
    __syncthreads();
    unsigned long long r = 0;
    if (threadIdx.x < NW) {
        r = sh[threadIdx.x];
        for (int o = NW / 2; o; o >>= 1) r += __shfl_down_sync((unsigned)((1ull << NW) - 1), r, o);
    }
    return r;
}

// 4-bit radix select over smem monot keys, stopping at STOPSHIFT (coarse bucket).
template <int STOPSHIFT>
__device__ unsigned radixSelectKeysSm(const unsigned* keys, int n, unsigned rank) {
    __shared__ unsigned cnts[8][16];
    __shared__ unsigned sPrefix, sRank;
    int tid = threadIdx.x, w = tid >> 5;
    if (tid == 0) { sPrefix = 0u; sRank = rank; }
    for (int shift = 28; shift >= STOPSHIFT; shift -= 4) {
        if (tid < 128) ((unsigned*)cnts)[tid] = 0u;
        __syncthreads();
        unsigned prefix = sPrefix;
        unsigned hiMask = (shift == 28) ? 0u : (0xFFFFFFFFu << (shift + 4));
        for (int i = tid; i < n; i += 256) {
            unsigned k = keys[i];
            if ((k & hiMask) == prefix) atomicAdd(&cnts[w][(k >> shift) & 15], 1u);
        }
        __syncthreads();
        if (tid == 0) {
            unsigned r = sRank, cum = 0;
            for (int d = 0; d < 16; d++) {
                unsigned c = 0;
                for (int ww = 0; ww < 8; ww++) c += cnts[ww][d];
                if (cum + c > r) { sPrefix = prefix | ((unsigned)d << shift); sRank = r - cum; break; }
                cum += c;
            }
        }
        __syncthreads();
    }
    return sPrefix;
}

// full 8-pass select over global float array (256 threads)
__device__ unsigned radixSelectG(const float* vals, int n, unsigned rank) {
    __shared__ unsigned cnts[8][16];
    __shared__ unsigned sPrefix, sRank;
    int tid = threadIdx.x, w = tid >> 5;
    if (tid == 0) { sPrefix = 0u; sRank = rank; }
    for (int shift = 28; shift >= 0; shift -= 4) {
        if (tid < 128) ((unsigned*)cnts)[tid] = 0u;
        __syncthreads();
        unsigned prefix = sPrefix;
        unsigned hiMask = (shift == 28) ? 0u : (0xFFFFFFFFu << (shift + 4));
        for (int i = tid; i < n; i += 256) {
            unsigned k = monot(vals[i]);
            if ((k & hiMask) == prefix) atomicAdd(&cnts[w][(k >> shift) & 15], 1u);
        }
        __syncthreads();
        if (tid == 0) {
            unsigned r = sRank, cum = 0;
            for (int d = 0; d < 16; d++) {
                unsigned c = 0;
                for (int ww = 0; ww < 8; ww++) c += cnts[ww][d];
                if (cum + c > r) { sPrefix = prefix | ((unsigned)d << shift); sRank = r - cum; break; }
                cum += c;
            }
        }
        __syncthreads();
    }
    return sPrefix;
}

// masked radix select over one image of a global tensor (256 threads; fallback path)
__device__ unsigned radixSelectMaskedG(const float* src, const void* M, int base, int mode, unsigned rank) {
    __shared__ unsigned cnts[8][16];
    __shared__ unsigned sPrefix, sRank;
    int tid = threadIdx.x, w = tid >> 5;
    if (tid == 0) { sPrefix = 0u; sRank = rank; }
    for (int shift = 28; shift >= 0; shift -= 4) {
        if (tid < 128) ((unsigned*)cnts)[tid] = 0u;
        __syncthreads();
        unsigned prefix = sPrefix;
        unsigned hiMask = (shift == 28) ? 0u : (0xFFFFFFFFu << (shift + 4));
        for (int i = tid; i < HWSZ; i += 256) {
            if (!maskRT(M, base + i, mode)) continue;
            unsigned k = monot(src[base + i]);
            if ((k & hiMask) == prefix) atomicAdd(&cnts[w][(k >> shift) & 15], 1u);
        }
        __syncthreads();
        if (tid == 0) {
            unsigned r = sRank, cum = 0;
            for (int d = 0; d < 16; d++) {
                unsigned c = 0;
                for (int ww = 0; ww < 8; ww++) c += cnts[ww][d];
                if (cum + c > r) { sPrefix = prefix | ((unsigned)d << shift); sRank = r - cum; break; }
                cum += c;
            }
        }
        __syncthreads();
    }
    return sPrefix;
}

// median+MAD finalize for one tensor t; block-collective (256 threads).
__device__ __noinline__ void select_one(int t, const float* P, const float* Y, const void* M) {
    __shared__ double redD[8];
    __shared__ unsigned long long redU[8];
    __shared__ int sFB;
    int img = t >> 1, tid = threadIdx.x;
    unsigned cnt = g_cnt[img];
    if (cnt == 0) { if (tid == 0) { g_med[t] = 0.f; g_isc[t] = (float)(1.0 / EPSV); } return; }
    unsigned r = (cnt - 1) >> 1;
    if (tid == 0) {
        int fb = g_flag[t];
        if (!fb) {
            unsigned nb_lo = g_nb[t];
            unsigned ncand = g_ccnt[t];
            long long j = (long long)r - (long long)nb_lo;
            if (ncand > CAP || j < 0 || j >= (long long)ncand) fb = 1;
        }
        sFB = fb;
    }
    __syncthreads();
    if (!sFB) {
        unsigned nb_lo = g_nb[t];
        unsigned ncand = g_ccnt[t];
        unsigned j = r - nb_lo;
        unsigned mkey = radixSelectG(g_cand[t], (int)ncand, j);
        unsigned nl = 0;
        double sl = 0;
        for (int i = tid; i < (int)ncand; i += 256) {
            float v = g_cand[t][i];
            if (monot(v) < mkey) { nl++; sl += (double)v; }
        }
        double sls = blockReduceD<256>(sl, redD);
        __syncthreads();
        unsigned long long nls = blockReduceU<256>(nl, redU);
        if (tid == 0) {
            double med = (double)inv_monot(mkey);
            double nb = (double)nb_lo + (double)nls;
            double Sb = g_sb[t] + sls;
            double abs_sum = g_stot[t] - 2.0 * Sb + med * (2.0 * nb - (double)cnt);
            if (abs_sum < 0.0) abs_sum = 0.0;
            double sc = abs_sum / (double)cnt + EPSV;
            g_med[t] = (float)med;
            g_isc[t] = (float)(1.0 / sc);
        }
        __syncthreads();
        return;
    }
    // exact fallback: masked radix select + one stats pass (normally dead)
    int mode = g_mmode;
    const float* src = (t & 1) ? Y : P;
    int base = img * HWSZ;
    unsigned mkey = radixSelectMaskedG(src, M, base, mode, r);
    unsigned nb = 0;
    double Sb = 0;
    for (int i = tid; i < HWSZ; i += 256) {
        if (!maskRT(M, base + i, mode)) continue;
        float v = src[base + i];
        if (monot(v) < mkey) { nb++; Sb += (double)v; }
    }
    double sbs = blockReduceD<256>(Sb, redD);
    __syncthreads();
    unsigned long long nbs = blockReduceU<256>(nb, redU);
    if (tid == 0) {
        double med = (double)inv_monot(mkey);
        double abs_sum = g_stot[t] - 2.0 * sbs + med * (2.0 * (double)nbs - (double)cnt);
        if (abs_sum < 0.0) abs_sum = 0.0;
        double sc = abs_sum / (double)cnt + EPSV;
        g_med[t] = (float)med;
        g_isc[t] = (float)(1.0 / sc);
    }
    __syncthreads();
}

// ---------------- kernels ----------------
// k_prep: init globals + per-(img,tensor) sampling + coarse quantile window. 128 blocks.
__global__ void __launch_bounds__(256) k_prep(const float* P, const float* Y, const void* M) {
    __shared__ unsigned skeys[SAMPN];
    __shared__ unsigned sN;
    __shared__ int sMode;
    int t = blockIdx.x, img = t >> 1, tid = threadIdx.x;
    if (tid == 0) {
        const unsigned char* b = (const unsigned char*)M;
        bool nonbin = false, offnz = false;
        for (int j = 0; j < 256; j++) {
            unsigned char v = b[j];
            if (v > 1) nonbin = true;
            if ((j & 3) && v) offnz = true;
        }
        int mode = nonbin ? 1 : (offnz ? 0 : 2);
        sMode = mode;
        if (t == 0) g_mmode = mode;
        sN = 0u;
    }
    if (tid == 1) { g_nb[t] = 0u; g_sb[t] = 0.0; g_stot[t] = 0.0; g_ccnt[t] = 0u; g_flag[t] = 0; }
    if (tid == 2 && (t & 1) == 0) { g_cnt[img] = 0u; g_rho[img] = 0.0; g_done[img] = 0u; }
    if (t == 0 && tid >= 8 && tid < 12) {
        int s = tid - 8;
        g_gx[s] = 0.0; g_gy[s] = 0.0; g_cx[s] = 0ull; g_cy[s] = 0ull;
    }
    __syncthreads();
    int mode = sMode;
    const float* src = (t & 1) ? Y : P;
    int base = img * HWSZ;
    for (int bt = 0; bt < 8; bt++) {
        float xv[4]; bool mv[4];
#pragma unroll
        for (int k = 0; k < 4; k++) {
            int idx = base + (bt * 4 + k) * SSTRIDE + tid;
            xv[k] = src[idx];
            mv[k] = maskRT(M, idx, mode);
        }
#pragma unroll
        for (int k = 0; k < 4; k++) {
            unsigned bal = __ballot_sync(0xffffffffu, mv[k]);
            if (bal) {
                int lane = tid & 31;
                unsigned pos = 0;
                int leader = __ffs(bal) - 1;
                if (lane == leader) pos = atomicAdd(&sN, (unsigned)__popc(bal));
                pos = __shfl_sync(0xffffffffu, pos, leader);
                if (mv[k]) skeys[pos + __popc(bal & ((1u << lane) - 1))] = monot(xv[k]);
            }
        }
    }
    __syncthreads();
    int n = (int)sN;
    if (n == 0) {
        if (tid == 0) { g_vlo[t] = __int_as_float(0x7f800000); g_vhi[t] = __int_as_float(0xff800000); }
        return;
    }
    unsigned rlo = (unsigned)(((long long)(n - 1) * 475) / 1000);
    unsigned rhi = (unsigned)((((long long)(n - 1) * 525) + 999) / 1000);
    if (rhi > (unsigned)(n - 1)) rhi = (unsigned)(n - 1);
    unsigned klo = radixSelectKeysSm<16>(skeys, n, rlo);
    unsigned khi = radixSelectKeysSm<16>(skeys, n, rhi) | 0xFFFFu;
    if (tid == 0) { g_vlo[t] = inv_monot(klo); g_vhi[t] = inv_monot(khi); }
}

struct ScanShared {
    float slotP[256 * SLOTS];
    float slotY[256 * SLOTS];
    unsigned wS[8];
    unsigned sBP, sBY;
    double redD[8];
    unsigned long long redU[8];
};

template <int MODE>
__device__ __forceinline__ void scan_impl(const float* P, const float* Y, const void* M, ScanShared* sh) {
    int img = blockIdx.y, bx = blockIdx.x, tid = threadIdx.x;
    int s = (bx * G8) >> 5;
    int e = ((bx + 1) * G8) >> 5;
    int iters = ((e - s) + 255) >> 8;
    float vloP = g_vlo[2 * img], vhiP = g_vhi[2 * img];
    float vloY = g_vlo[2 * img + 1], vhiY = g_vhi[2 * img + 1];
    const float4* P4 = (const float4*)P;
    const float4* Y4 = (const float4*)Y;
    float* myP = sh->slotP + tid * SLOTS;
    float* myY = sh->slotY + tid * SLOTS;
    unsigned cnt = 0, nbP = 0, nbY = 0, mcP = 0, mcY = 0;
    float sbP = 0.f, sbY = 0.f, stP = 0.f, stY = 0.f;
    for (int it = 0; it < iters; it++) {
        int g = s + it * 256 + tid;
        bool ok = g < e;
        int idx4 = img * HW4 + 2 * (ok ? g : s);
        float4 p0 = P4[idx4], p1 = P4[idx4 + 1];
        float4 q0 = Y4[idx4], q1 = Y4[idx4 + 1];
        float pv[8] = {p0.x, p0.y, p0.z, p0.w, p1.x, p1.y, p1.z, p1.w};
        float qv[8] = {q0.x, q0.y, q0.z, q0.w, q1.x, q1.y, q1.z, q1.w};
        bool mv[8];
        if (MODE == 0) {
            const unsigned* Mu = (const unsigned*)M;
            unsigned ma = Mu[idx4], mb = Mu[idx4 + 1];
#pragma unroll
            for (int j = 0; j < 4; j++) { mv[j] = (ma >> (8 * j)) & 0xffu; mv[4 + j] = (mb >> (8 * j)) & 0xffu; }
        } else {
            loadMask4<MODE>(M, idx4, mv[0], mv[1], mv[2], mv[3]);
            loadMask4<MODE>(M, idx4 + 1, mv[4], mv[5], mv[6], mv[7]);
        }
#pragma unroll
        for (int j = 0; j < 8; j++) {
            if (ok && mv[j]) {
                cnt++;
                float a = pv[j];
                stP += a;
                if (a < vloP) { nbP++; sbP += a; }
                else if (a <= vhiP) { if (mcP < SLOTS) myP[mcP] = a; mcP++; }
                float b = qv[j];
                stY += b;
                if (b < vloY) { nbY++; sbY += b; }
                else if (b <= vhiY) { if (mcY < SLOTS) myY[mcY] = b; mcY++; }
            }
        }
    }
    if (bx == 31 && tid < 4) {
        int ei = img * HWSZ + G8 * 8 + tid;
        if (maskAt<MODE>(M, ei)) {
            cnt++;
            float a = P[ei];
            stP += a;
            if (a < vloP) { nbP++; sbP += a; }
            else if (a <= vhiP) { if (mcP < SLOTS) myP[mcP] = a; mcP++; }
            float b = Y[ei];
            stY += b;
            if (b < vloY) { nbY++; sbY += b; }
            else if (b <= vhiY) { if (mcY < SLOTS) myY[mcY] = b; mcY++; }
        }
    }
    int ovf = __syncthreads_or((mcP > SLOTS) | (mcY > SLOTS));
    unsigned nP = min(mcP, (unsigned)SLOTS), nY = min(mcY, (unsigned)SLOTS);
    double r;
    r = blockReduceD<256>((double)sbP, sh->redD); if (tid == 0) atomicAdd(&g_sb[2 * img], r); __syncthreads();
    r = blockReduceD<256>((double)sbY, sh->redD); if (tid == 0) atomicAdd(&g_sb[2 * img + 1], r); __syncthreads();
    r = blockReduceD<256>((double)stP, sh->redD); if (tid == 0) atomicAdd(&g_stot[2 * img], r); __syncthreads();
    r = blockReduceD<256>((double)stY, sh->redD); if (tid == 0) atomicAdd(&g_stot[2 * img + 1], r); __syncthreads();
    unsigned long long u;
    u = blockReduceU<256>(cnt, sh->redU); if (tid == 0) atomicAdd(&g_cnt[img], (unsigned)u); __syncthreads();
    u = blockReduceU<256>(nbP, sh->redU); if (tid == 0) atomicAdd(&g_nb[2 * img], (unsigned)u); __syncthreads();
    u = blockReduceU<256>(nbY, sh->redU); if (tid == 0) atomicAdd(&g_nb[2 * img + 1], (unsigned)u);
    __syncthreads();
    // packed prefix scan of (nP | nY<<16)
    int lane = tid & 31, w = tid >> 5;
    unsigned myc = nP | (nY << 16);
    unsigned inc = myc;
    for (int o = 1; o < 32; o <<= 1) {
        unsigned v2 = __shfl_up_sync(0xffffffffu, inc, o);
        if (lane >= o) inc += v2;
    }
    if (lane == 31) sh->wS[w] = inc;
    __syncthreads();
    if (tid < 8) {
        unsigned v2 = sh->wS[tid];
        for (int o = 1; o < 8; o <<= 1) {
            unsigned v3 = __shfl_up_sync(0xffu, v2, o);
            if (tid >= o) v2 += v3;
        }
        sh->wS[tid] = v2;
    }
    __syncthreads();
    unsigned exc = ((w > 0) ? sh->wS[w - 1] : 0u) + inc - myc;
    unsigned tot = sh->wS[7];
    unsigned preP = exc & 0xffffu, preY = exc >> 16;
    unsigned totP = tot & 0xffffu, totY = tot >> 16;
    if (tid == 0) {
        sh->sBP = atomicAdd(&g_ccnt[2 * img], totP);
        sh->sBY = atomicAdd(&g_ccnt[2 * img + 1], totY);
        if (ovf) { g_flag[2 * img] = 1; g_flag[2 * img + 1] = 1; }
    }
    __syncthreads();
    float* candP = g_cand[2 * img];
    float* candY = g_cand[2 * img + 1];
    for (unsigned k = 0; k < nP; k++) { unsigned o = sh->sBP + preP + k; if (o < CAP) candP[o] = myP[k]; }
    for (unsigned k = 0; k < nY; k++) { unsigned o = sh->sBY + preY + k; if (o < CAP) candY[o] = myY[k]; }
}
__global__ void __launch_bounds__(256) k_scan(const float* P, const float* Y, const void* M) {
    __shared__ ScanShared sh;    // single instance shared across instantiations
    int m = g_mmode;
    if (m == 0) scan_impl<0>(P, Y, M, &sh);
    else if (m == 2) scan_impl<2>(P, Y, M, &sh);
    else scan_impl<1>(P, Y, M, &sh);
    // last-block-per-image: run select inline (removes k_select launch)
    __shared__ int sLast;
    __threadfence();
    if (threadIdx.x == 0) sLast = (atomicAdd(&g_done[blockIdx.y], 1u) == 31u) ? 1 : 0;
    __syncthreads();
    if (!sLast) return;
    select_one(2 * blockIdx.y, P, Y, M);
    select_one(2 * blockIdx.y + 1, P, Y, M);
}

struct __align__(16) MainShared {
    float sd[15 * ROWP];
    unsigned char sm[15 * ROWP];
    double redD[16];
    unsigned long long redU[16];
};

template <int MODE>
__device__ __forceinline__ void main_impl(const float* P, const float* Y, const void* M, MainShared* sh) {
    float* sd = sh->sd;
    unsigned char* sm = sh->sm;
    int tid = threadIdx.x;
    const float2* P2 = (const float2*)P;
    const float2* Y2 = (const float2*)Y;
    for (int t = blockIdx.x; t < NTILES; t += MAINGRID) {   // exactly 4 uniform iterations
        int img = t / NBANDS;
        int band = t - img * NBANDS;
        bool last = (band == NBANDS - 1);
        int nrows = last ? 14 : 15;
        float medp = g_med[2 * img], medy = g_med[2 * img + 1];
        float iscp = g_isc[2 * img], iscy = g_isc[2 * img + 1];
        int ebase = img * HWSZ + band * BANDSZ;
        int base2 = ebase >> 1;
        for (int f = tid; f < nrows * 259; f += 512) {
            int r = f / 259, j = f - 259 * r;
            int g2 = base2 + r * 259 + j;
            float2 p = P2[g2], q = Y2[g2];
            bool m0, m1;
            loadMask2<MODE>(M, g2, m0, m1);
            int o = r * ROWP + 2 * j;
            float2 dv;
            dv.x = (p.x - medp) * iscp - (q.x - medy) * iscy;
            dv.y = (p.y - medp) * iscp - (q.y - medy) * iscy;
            *(float2*)(sd + o) = dv;
            uchar2 mm; mm.x = m0 ? 1 : 0; mm.y = m1 ? 1 : 0;
            *(uchar2*)(sm + o) = mm;
        }
        if (tid < 15) {
            int o = tid * ROWP + 518;
            sd[o] = 0.f; sd[o + 1] = 0.f; sm[o] = 0; sm[o + 1] = 0;
        }
        if (last) {
            for (int z = tid; z < ROWP; z += 512) { sd[14 * ROWP + z] = 0.f; sm[14 * ROWP + z] = 0; }
        }
        __syncthreads();
        float rho = 0.f, gx = 0.f, gy = 0.f;
        unsigned cx = 0, cy = 0;
        int nprow = last ? 13 : 14;
        for (int g = tid; g < 14 * 130; g += 512) {
            int row = g / 130, gi = g - 130 * row;
            int b = row * ROWP + 4 * gi;
            float4 a = *(const float4*)(sd + b);
            float a4 = sd[b + 4];
            uchar4 mk = *(const uchar4*)(sm + b);
            unsigned char mk4 = sm[b + 4];
            if (mk.x) rho += fabsf(a.x);
            if (mk.y) rho += fabsf(a.y);
            if (mk.z) rho += fabsf(a.z);
            if (mk.w) rho += fabsf(a.w);
            if (mk.x && mk.y) { gx += fabsf(a.y - a.x); cx++; }
            if (mk.y && mk.z) { gx += fabsf(a.z - a.y); cx++; }
            if (mk.z && mk.w) { gx += fabsf(a.w - a.z); cx++; }
            if (mk.w && mk4)  { gx += fabsf(a4 - a.w); cx++; }
            if (row < nprow) {
                float4 c = *(const float4*)(sd + b + ROWP);
                uchar4 mc = *(const uchar4*)(sm + b + ROWP);
                if (mk.x && mc.x) { gy += fabsf(c.x - a.x); cy++; }
                if (mk.y && mc.y) { gy += fabsf(c.y - a.y); cy++; }
                if (mk.z && mc.z) { gy += fabsf(c.z - a.z); cy++; }
                if (mk.w && mc.w) { gy += fabsf(c.w - a.w); cy++; }
            }
        }
        float* d1 = d1buf + img * L1SZ + band * 7 * L1W;
        unsigned char* m1 = m1buf + img * L1SZ + band * 7 * L1W;
        for (int pi = tid; pi < 7 * L1W; pi += 512) {
            int pr = pi / L1W, pc = pi - pr * L1W;
            int o0 = (2 * pr) * ROWP + 2 * pc;
            float2 tp = *(const float2*)(sd + o0);
            float2 bt = *(const float2*)(sd + o0 + ROWP);
            uchar2 mt = *(const uchar2*)(sm + o0);
            uchar2 mb = *(const uchar2*)(sm + o0 + ROWP);
            d1[pi] = 0.25f * ((tp.x + tp.y) + (bt.x + bt.y));
            m1[pi] = (unsigned char)(mt.x | mt.y | mb.x | mb.y);
        }
        double r1 = blockReduceD<512>((double)rho, sh->redD); __syncthreads();
        double r2 = blockReduceD<512>((double)gx, sh->redD);  __syncthreads();
        double r3 = blockReduceD<512>((double)gy, sh->redD);  __syncthreads();
        unsigned long long u1 = blockReduceU<512>(cx, sh->redU); __syncthreads();
        unsigned long long u2 = blockReduceU<512>(cy, sh->redU);
        if (tid == 0) {
            atomicAdd(&g_rho[img], r1);
            atomicAdd(&g_gx[0], r2); atomicAdd(&g_gy[0], r3);
            atomicAdd(&g_cx[0], u1); atomicAdd(&g_cy[0], u2);
        }
        __syncthreads();   // orders smem reuse for next tile
    }
}
__global__ void __launch_bounds__(512) k_main(const float* P, const float* Y, const void* M) {
    __shared__ MainShared sh;    // single instance shared across instantiations
    int m = g_mmode;
    if (m == 0) main_impl<0>(P, Y, M, &sh);
    else if (m == 2) main_impl<2>(P, Y, M, &sh);
    else main_impl<1>(P, Y, M, &sh);
}

// grad level 1 + pool L1 -> L2 (global). 1024 blocks.
__global__ void __launch_bounds__(256) k_gp1() {
    const float* d = d1buf;
    const unsigned char* m = m1buf;
    float* dout = d2buf;
    unsigned char* mo = m2buf;
    __shared__ double redD[8];
    __shared__ unsigned long long redU[8];
    constexpr int per = 259 * 259;
    constexpr int total = NIMG * per;
    float gx = 0.f, gy = 0.f;
    unsigned cx = 0, cy = 0;
    for (int i = blockIdx.x * blockDim.x + threadIdx.x; i < total; i += gridDim.x * blockDim.x) {
        if (!m[i]) continue;
        int rem = i % per;
        int r = rem / 259, c = rem - r * 259;
        float dv = d[i];
        if (c < 258 && m[i + 1]) { gx += fabsf(d[i + 1] - dv); cx++; }
        if (r < 258 && m[i + 259]) { gy += fabsf(d[i + 259] - dv); cy++; }
    }
    constexpr int perO = 129 * 129;
    constexpr int totalO = NIMG * perO;
    for (int i = blockIdx.x * blockDim.x + threadIdx.x; i < totalO; i += gridDim.x * blockDim.x) {
        int img = i / perO, rem = i - img * perO;
        int r = rem / 129, c = rem - r * 129;
        int bi = img * per + (2 * r) * 259 + 2 * c;
        dout[i] = 0.25f * (d[bi] + d[bi + 1] + d[bi + 259] + d[bi + 260]);
        mo[i] = m[bi] | m[bi + 1] | m[bi + 259] | m[bi + 260];
    }
    double r2 = blockReduceD<256>((double)gx, redD); __syncthreads();
    double r3 = blockReduceD<256>((double)gy, redD); __syncthreads();
    unsigned long long u1 = blockReduceU<256>(cx, redU); __syncthreads();
    unsigned long long u2 = blockReduceU<256>(cy, redU);
    if (threadIdx.x == 0) {
        atomicAdd(&g_gx[1], r2); atomicAdd(&g_gy[1], r3);
        atomicAdd(&g_cx[1], u1); atomicAdd(&g_cy[1], u2);
    }
}

// fused tail2: grad L2 (gmem, L2-hot) + pool L2->L3 (smem) + grad L3 (smem). 64 blocks.
__global__ void __launch_bounds__(512) k_tail2() {
    __shared__ float d3s[64 * 64];
    __shared__ unsigned char m3s[64 * 64];
    __shared__ double redD[16];
    __shared__ unsigned long long redU[16];
    int img = blockIdx.x, tid = threadIdx.x;
    const float* d2 = d2buf + img * 129 * 129;
    const unsigned char* m2 = m2buf + img * 129 * 129;
    float gx2 = 0.f, gy2 = 0.f;
    unsigned cx2 = 0, cy2 = 0;
    for (int i = tid; i < 129 * 129; i += 512) {
        if (!m2[i]) continue;
        int r = i / 129, c = i - 129 * r;
        float dv = d2[i];
        if (c < 128 && m2[i + 1]) { gx2 += fabsf(d2[i + 1] - dv); cx2++; }
        if (r < 128 && m2[i + 129]) { gy2 += fabsf(d2[i + 129] - dv); cy2++; }
    }
    for (int i = tid; i < 64 * 64; i += 512) {
        int r = i >> 6, c = i & 63;
        int bi = 2 * r * 129 + 2 * c;
        d3s[i] = 0.25f * (d2[bi] + d2[bi + 1] + d2[bi + 129] + d2[bi + 130]);
        m3s[i] = (unsigned char)(m2[bi] | m2[bi + 1] | m2[bi + 129] | m2[bi + 130]);
    }
    __syncthreads();
    float gx3 = 0.f, gy3 = 0.f;
    unsigned cx3 = 0, cy3 = 0;
    for (int i = tid; i < 64 * 64; i += 512) {
        if (!m3s[i]) continue;
        int r = i >> 6, c = i & 63;
        float dv = d3s[i];
        if (c < 63 && m3s[i + 1]) { gx3 += fabsf(d3s[i + 1] - dv); cx3++; }
        if (r < 63 && m3s[i + 64]) { gy3 += fabsf(d3s[i + 64] - dv); cy3++; }
    }
    double v;
    v = blockReduceD<512>((double)gx2, redD); if (tid == 0) atomicAdd(&g_gx[2], v); __syncthreads();
    v = blockReduceD<512>((double)gy2, redD); if (tid == 0) atomicAdd(&g_gy[2], v); __syncthreads();
    v = blockReduceD<512>((double)gx3, redD); if (tid == 0) atomicAdd(&g_gx[3], v); __syncthreads();
    v = blockReduceD<512>((double)gy3, redD); if (tid == 0) atomicAdd(&g_gy[3], v); __syncthreads();
    unsigned long long u;
    u = blockReduceU<512>(cx2, redU); if (tid == 0) atomicAdd(&g_cx[2], u); __syncthreads();
    u = blockReduceU<512>(cy2, redU); if (tid == 0) atomicAdd(&g_cy[2], u); __syncthreads();
    u = blockReduceU<512>(cx3, redU); if (tid == 0) atomicAdd(&g_cx[3], u); __syncthreads();
    u = blockReduceU<512>(cy3, redU); if (tid == 0) atomicAdd(&g_cy[3], u);
}

__global__ void k_final(float* out) {
    if (threadIdx.x == 0 && blockIdx.x == 0) {
        double ssi = 0;
        for (int i = 0; i < NIMG; i++) {
            double v = (double)g_cnt[i];
            if (v < 1.0) v = 1.0;
            ssi += g_rho[i] / v;
        }
        ssi /= (double)NIMG;
        double g = 0;
        for (int s = 0; s < 4; s++) {
            double cx = (double)g_cx[s]; if (cx < 1.0) cx = 1.0;
            double cy = (double)g_cy[s]; if (cy < 1.0) cy = 1.0;
            g += g_gx[s] / cx + g_gy[s] / cy;
        }
        out[0] = (float)(ssi + 0.5 * (g / 4.0));
    }
}

extern "C" void kernel_launch(void* const* d_in, const int* in_sizes, int n_in,
                              void* d_out, int out_size) {
    const float* pred = (const float*)d_in[0];
    const float* yv = (const float*)d_in[1];
    const void* mask = d_in[2];
    float* out = (float*)d_out;

    k_prep<<<128, 256>>>(pred, yv, mask);
    k_scan<<<dim3(32, NIMG), 256>>>(pred, yv, mask);
    k_main<<<MAINGRID, 512>>>(pred, yv, mask);
    k_gp1<<<1024, 256>>>();
    k_tail2<<<64, 512>>>();
    k_final<<<1, 32>>>(out);
}

// round 12
// speedup vs baseline: 1.4242x; 1.4242x over previous
#include <cuda_runtime.h>
#include <cstdint>

#define HWSZ 268324
#define HW4  67081
#define WD 518
#define ROWP 520
#define NIMG 64
#define CAP 32768
#define SLOTS 12
#define EPSV 1e-8
#define SAMPN 8192
#define SSTRIDE 8385
#define BANDSZ 7252        // 14 rows * 518
#define NBANDS 37
#define NTILES (NBANDS * NIMG)   // 2368
#define MAINGRID 592             // 2368 / 4
#define L1W 259
#define L1SZ (259*259)
#define G8 33540           // full 8-element groups per image

// ---------------- static device scratch ----------------
__device__ int g_mmode;
__device__ float g_vlo[128], g_vhi[128];
__device__ int g_flag[128];
__device__ unsigned g_cnt[NIMG];
__device__ unsigned g_nb[128];
__device__ double g_sb[128];
__device__ double g_stot[128];
__device__ unsigned g_ccnt[128];
__device__ float g_cand[128][CAP];
__device__ float g_med[128], g_isc[128];
__device__ double g_rho[NIMG];
__device__ double g_gx[4], g_gy[4];
__device__ unsigned long long g_cx[4], g_cy[4];

__device__ float d1buf[NIMG * L1SZ];
__device__ unsigned char m1buf[NIMG * L1SZ];
__device__ float d2buf[NIMG * 129 * 129];
__device__ unsigned char m2buf[NIMG * 129 * 129];

// ---------------- helpers ----------------
__device__ __forceinline__ unsigned monot(float x) {
    unsigned u = __float_as_uint(x);
    return (u >> 31) ? ~u : (u | 0x80000000u);
}
__device__ __forceinline__ float inv_monot(unsigned k) {
    unsigned u = (k >> 31) ? (k & 0x7FFFFFFFu) : ~k;
    return __uint_as_float(u);
}
__device__ __forceinline__ bool maskRT(const void* m, int i, int mode) {
    return (mode == 0) ? ((const unsigned char*)m)[i] != 0
         : (mode == 2) ? ((const int*)m)[i] != 0
         : ((const float*)m)[i] != 0.f;
}

template <int MODE>
__device__ __forceinline__ bool maskAt(const void* m, int i) {
    if (MODE == 0) return ((const unsigned char*)m)[i] != 0;
    if (MODE == 2) return ((const int*)m)[i] != 0;
    return ((const float*)m)[i] != 0.f;
}
template <int MODE>
__device__ __forceinline__ void loadMask4(const void* m, int g4, bool& b0, bool& b1, bool& b2, bool& b3) {
    if (MODE == 0) { uchar4 v = ((const uchar4*)m)[g4]; b0 = v.x; b1 = v.y; b2 = v.z; b3 = v.w; }
    else if (MODE == 2) { int4 v = ((const int4*)m)[g4]; b0 = v.x != 0; b1 = v.y != 0; b2 = v.z != 0; b3 = v.w != 0; }
    else { float4 v = ((const float4*)m)[g4]; b0 = v.x != 0.f; b1 = v.y != 0.f; b2 = v.z != 0.f; b3 = v.w != 0.f; }
}
template <int MODE>
__device__ __forceinline__ void loadMask2(const void* m, int g2, bool& b0, bool& b1) {
    if (MODE == 0) { uchar2 v = ((const uchar2*)m)[g2]; b0 = v.x; b1 = v.y; }
    else if (MODE == 2) { int2 v = ((const int2*)m)[g2]; b0 = v.x != 0; b1 = v.y != 0; }
    else { float2 v = ((const float2*)m)[g2]; b0 = v.x != 0.f; b1 = v.y != 0.f; }
}

template <int NT>
__device__ __forceinline__ double blockReduceD(double v, double* sh) {
    constexpr int NW = NT / 32;
    for (int o = 16; o; o >>= 1) v += __shfl_down_sync(0xffffffffu, v, o);
    int w = threadIdx.x >> 5, l = threadIdx.x & 31;
    if (l == 0) sh[w] = v;
    __syncthreads();
    double r = 0;
    if (threadIdx.x < NW) {
        r = sh[threadIdx.x];
        for (int o = NW / 2; o; o >>= 1) r += __shfl_down_sync((unsigned)((1ull << NW) - 1), r, o);
    }
    return r;
}
template <int NT>
__device__ __forceinline__ unsigned long long blockReduceU(unsigned long long v, unsigned long long* sh) {
    constexpr int NW = NT / 32;
    for (int o = 16; o; o >>= 1) v += __shfl_down_sync(0xffffffffu, v, o);
    int w = threadIdx.x >> 5, l = threadIdx.x & 31;
    if (l == 0) sh[w] = v;
    __syncthreads();
    unsigned long long r = 0;
    if (threadIdx.x < NW) {
        r = sh[threadIdx.x];
        for (int o = NW / 2; o; o >>= 1) r += __shfl_down_sync((unsigned)((1ull << NW) - 1), r, o);
    }
    return r;
}

// 4-bit radix select over smem monot keys, stopping at STOPSHIFT (coarse bucket).
template <int STOPSHIFT>
__device__ unsigned radixSelectKeysSm(const unsigned* keys, int n, unsigned rank) {
    __shared__ unsigned cnts[8][16];
    __shared__ unsigned sPrefix, sRank;
    int tid = threadIdx.x, w = tid >> 5;
    if (tid == 0) { sPrefix = 0u; sRank = rank; }
    for (int shift = 28; shift >= STOPSHIFT; shift -= 4) {
        if (tid < 128) ((unsigned*)cnts)[tid] = 0u;
        __syncthreads();
        unsigned prefix = sPrefix;
        unsigned hiMask = (shift == 28) ? 0u : (0xFFFFFFFFu << (shift + 4));
        for (int i = tid; i < n; i += 256) {
            unsigned k = keys[i];
            if ((k & hiMask) == prefix) atomicAdd(&cnts[w][(k >> shift) & 15], 1u);
        }
        __syncthreads();
        if (tid == 0) {
            unsigned r = sRank, cum = 0;
            for (int d = 0; d < 16; d++) {
                unsigned c = 0;
                for (int ww = 0; ww < 8; ww++) c += cnts[ww][d];
                if (cum + c > r) { sPrefix = prefix | ((unsigned)d << shift); sRank = r - cum; break; }
                cum += c;
            }
        }
        __syncthreads();
    }
    return sPrefix;
}

// full 8-pass select over global float array (256 threads)
__device__ unsigned radixSelectG(const float* vals, int n, unsigned rank) {
    __shared__ unsigned cnts[8][16];
    __shared__ unsigned sPrefix, sRank;
    int tid = threadIdx.x, w = tid >> 5;
    if (tid == 0) { sPrefix = 0u; sRank = rank; }
    for (int shift = 28; shift >= 0; shift -= 4) {
        if (tid < 128) ((unsigned*)cnts)[tid] = 0u;
        __syncthreads();
        unsigned prefix = sPrefix;
        unsigned hiMask = (shift == 28) ? 0u : (0xFFFFFFFFu << (shift + 4));
        for (int i = tid; i < n; i += 256) {
            unsigned k = monot(vals[i]);
            if ((k & hiMask) == prefix) atomicAdd(&cnts[w][(k >> shift) & 15], 1u);
        }
        __syncthreads();
        if (tid == 0) {
            unsigned r = sRank, cum = 0;
            for (int d = 0; d < 16; d++) {
                unsigned c = 0;
                for (int ww = 0; ww < 8; ww++) c += cnts[ww][d];
                if (cum + c > r) { sPrefix = prefix | ((unsigned)d << shift); sRank = r - cum; break; }
                cum += c;
            }
        }
        __syncthreads();
    }
    return sPrefix;
}

// masked radix select over one image of a global tensor (256 threads; fallback path)
__device__ unsigned radixSelectMaskedG(const float* src, const void* M, int base, int mode, unsigned rank) {
    __shared__ unsigned cnts[8][16];
    __shared__ unsigned sPrefix, sRank;
    int tid = threadIdx.x, w = tid >> 5;
    if (tid == 0) { sPrefix = 0u; sRank = rank; }
    for (int shift = 28; shift >= 0; shift -= 4) {
        if (tid < 128) ((unsigned*)cnts)[tid] = 0u;
        __syncthreads();
        unsigned prefix = sPrefix;
        unsigned hiMask = (shift == 28) ? 0u : (0xFFFFFFFFu << (shift + 4));
        for (int i = tid; i < HWSZ; i += 256) {
            if (!maskRT(M, base + i, mode)) continue;
            unsigned k = monot(src[base + i]);
            if ((k & hiMask) == prefix) atomicAdd(&cnts[w][(k >> shift) & 15], 1u);
        }
        __syncthreads();
        if (tid == 0) {
            unsigned r = sRank, cum = 0;
            for (int d = 0; d < 16; d++) {
                unsigned c = 0;
                for (int ww = 0; ww < 8; ww++) c += cnts[ww][d];
                if (cum + c > r) { sPrefix = prefix | ((unsigned)d << shift); sRank = r - cum; break; }
                cum += c;
            }
        }
        __syncthreads();
    }
    return sPrefix;
}

// ---------------- kernels ----------------
// k_prep: init globals + per-(img,tensor) sampling + coarse quantile window. 128 blocks.
__global__ void __launch_bounds__(256) k_prep(const float* P, const float* Y, const void* M) {
    __shared__ unsigned skeys[SAMPN];
    __shared__ unsigned sN;
    __shared__ int sMode;
    int t = blockIdx.x, img = t >> 1, tid = threadIdx.x;
    if (tid == 0) {
        const unsigned char* b = (const unsigned char*)M;
        bool nonbin = false, offnz = false;
        for (int j = 0; j < 256; j++) {
            unsigned char v = b[j];
            if (v > 1) nonbin = true;
            if ((j & 3) && v) offnz = true;
        }
        int mode = nonbin ? 1 : (offnz ? 0 : 2);
        sMode = mode;
        if (t == 0) g_mmode = mode;
        sN = 0u;
    }
    if (tid == 1) { g_nb[t] = 0u; g_sb[t] = 0.0; g_stot[t] = 0.0; g_ccnt[t] = 0u; g_flag[t] = 0; }
    if (tid == 2 && (t & 1) == 0) { g_cnt[img] = 0u; g_rho[img] = 0.0; }
    if (t == 0 && tid >= 8 && tid < 12) {
        int s = tid - 8;
        g_gx[s] = 0.0; g_gy[s] = 0.0; g_cx[s] = 0ull; g_cy[s] = 0ull;
    }
    __syncthreads();
    int mode = sMode;
    const float* src = (t & 1) ? Y : P;
    int base = img * HWSZ;
    for (int bt = 0; bt < 8; bt++) {
        float xv[4]; bool mv[4];
#pragma unroll
        for (int k = 0; k < 4; k++) {
            int idx = base + (bt * 4 + k) * SSTRIDE + tid;
            xv[k] = src[idx];
            mv[k] = maskRT(M, idx, mode);
        }
#pragma unroll
        for (int k = 0; k < 4; k++) {
            unsigned bal = __ballot_sync(0xffffffffu, mv[k]);
            if (bal) {
                int lane = tid & 31;
                unsigned pos = 0;
                int leader = __ffs(bal) - 1;
                if (lane == leader) pos = atomicAdd(&sN, (unsigned)__popc(bal));
                pos = __shfl_sync(0xffffffffu, pos, leader);
                if (mv[k]) skeys[pos + __popc(bal & ((1u << lane) - 1))] = monot(xv[k]);
            }
        }
    }
    __syncthreads();
    int n = (int)sN;
    if (n == 0) {
        if (tid == 0) { g_vlo[t] = __int_as_float(0x7f800000); g_vhi[t] = __int_as_float(0xff800000); }
        return;
    }
    unsigned rlo = (unsigned)(((long long)(n - 1) * 475) / 1000);
    unsigned rhi = (unsigned)((((long long)(n - 1) * 525) + 999) / 1000);
    if (rhi > (unsigned)(n - 1)) rhi = (unsigned)(n - 1);
    // coarse (top-16-bit) buckets: take bucket lower bound for lo, upper bound for hi.
    unsigned klo = radixSelectKeysSm<16>(skeys, n, rlo);
    unsigned khi = radixSelectKeysSm<16>(skeys, n, rhi) | 0xFFFFu;
    if (tid == 0) { g_vlo[t] = inv_monot(klo); g_vhi[t] = inv_monot(khi); }
}

struct ScanShared {
    float slotP[256 * SLOTS];
    float slotY[256 * SLOTS];
    unsigned wS[8];
    unsigned sBP, sBY;
    double redD[8];
    unsigned long long redU[8];
};

template <int MODE>
__device__ __forceinline__ void scan_impl(const float* P, const float* Y, const void* M, ScanShared* sh) {
    int img = blockIdx.y, bx = blockIdx.x, tid = threadIdx.x;
    int s = (bx * G8) >> 5;
    int e = ((bx + 1) * G8) >> 5;
    int iters = ((e - s) + 255) >> 8;
    float vloP = g_vlo[2 * img], vhiP = g_vhi[2 * img];
    float vloY = g_vlo[2 * img + 1], vhiY = g_vhi[2 * img + 1];
    const float4* P4 = (const float4*)P;
    const float4* Y4 = (const float4*)Y;
    float* myP = sh->slotP + tid * SLOTS;
    float* myY = sh->slotY + tid * SLOTS;
    unsigned cnt = 0, nbP = 0, nbY = 0, mcP = 0, mcY = 0;
    float sbP = 0.f, sbY = 0.f, stP = 0.f, stY = 0.f;
    for (int it = 0; it < iters; it++) {
        int g = s + it * 256 + tid;
        bool ok = g < e;
        int idx4 = img * HW4 + 2 * (ok ? g : s);
        float4 p0 = P4[idx4], p1 = P4[idx4 + 1];
        float4 q0 = Y4[idx4], q1 = Y4[idx4 + 1];
        float pv[8] = {p0.x, p0.y, p0.z, p0.w, p1.x, p1.y, p1.z, p1.w};
        float qv[8] = {q0.x, q0.y, q0.z, q0.w, q1.x, q1.y, q1.z, q1.w};
        bool mv[8];
        if (MODE == 0) {
            const unsigned* Mu = (const unsigned*)M;
            unsigned ma = Mu[idx4], mb = Mu[idx4 + 1];
#pragma unroll
            for (int j = 0; j < 4; j++) { mv[j] = (ma >> (8 * j)) & 0xffu; mv[4 + j] = (mb >> (8 * j)) & 0xffu; }
        } else {
            loadMask4<MODE>(M, idx4, mv[0], mv[1], mv[2], mv[3]);
            loadMask4<MODE>(M, idx4 + 1, mv[4], mv[5], mv[6], mv[7]);
        }
#pragma unroll
        for (int j = 0; j < 8; j++) {
            if (ok && mv[j]) {
                cnt++;
                float a = pv[j];
                stP += a;
                if (a < vloP) { nbP++; sbP += a; }
                else if (a <= vhiP) { if (mcP < SLOTS) myP[mcP] = a; mcP++; }
                float b = qv[j];
                stY += b;
                if (b < vloY) { nbY++; sbY += b; }
                else if (b <= vhiY) { if (mcY < SLOTS) myY[mcY] = b; mcY++; }
            }
        }
    }
    // tail: 4 leftover elements per image (block 31, per-thread, no collectives)
    if (bx == 31 && tid < 4) {
        int ei = img * HWSZ + G8 * 8 + tid;
        if (maskAt<MODE>(M, ei)) {
            cnt++;
            float a = P[ei];
            stP += a;
            if (a < vloP) { nbP++; sbP += a; }
            else if (a <= vhiP) { if (mcP < SLOTS) myP[mcP] = a; mcP++; }
            float b = Y[ei];
            stY += b;
            if (b < vloY) { nbY++; sbY += b; }
            else if (b <= vhiY) { if (mcY < SLOTS) myY[mcY] = b; mcY++; }
        }
    }
    int ovf = __syncthreads_or((mcP > SLOTS) | (mcY > SLOTS));
    unsigned nP = min(mcP, (unsigned)SLOTS), nY = min(mcY, (unsigned)SLOTS);
    double r;
    r = blockReduceD<256>((double)sbP, sh->redD); if (tid == 0) atomicAdd(&g_sb[2 * img], r); __syncthreads();
    r = blockReduceD<256>((double)sbY, sh->redD); if (tid == 0) atomicAdd(&g_sb[2 * img + 1], r); __syncthreads();
    r = blockReduceD<256>((double)stP, sh->redD); if (tid == 0) atomicAdd(&g_stot[2 * img], r); __syncthreads();
    r = blockReduceD<256>((double)stY, sh->redD); if (tid == 0) atomicAdd(&g_stot[2 * img + 1], r); __syncthreads();
    unsigned long long u;
    u = blockReduceU<256>(cnt, sh->redU); if (tid == 0) atomicAdd(&g_cnt[img], (unsigned)u); __syncthreads();
    u = blockReduceU<256>(nbP, sh->redU); if (tid == 0) atomicAdd(&g_nb[2 * img], (unsigned)u); __syncthreads();
    u = blockReduceU<256>(nbY, sh->redU); if (tid == 0) atomicAdd(&g_nb[2 * img + 1], (unsigned)u);
    __syncthreads();
    // packed prefix scan of (nP | nY<<16)
    int lane = tid & 31, w = tid >> 5;
    unsigned myc = nP | (nY << 16);
    unsigned inc = myc;
    for (int o = 1; o < 32; o <<= 1) {
        unsigned v2 = __shfl_up_sync(0xffffffffu, inc, o);
        if (lane >= o) inc += v2;
    }
    if (lane == 31) sh->wS[w] = inc;
    __syncthreads();
    if (tid < 8) {
        unsigned v2 = sh->wS[tid];
        for (int o = 1; o < 8; o <<= 1) {
            unsigned v3 = __shfl_up_sync(0xffu, v2, o);
            if (tid >= o) v2 += v3;
        }
        sh->wS[tid] = v2;
    }
    __syncthreads();
    unsigned exc = ((w > 0) ? sh->wS[w - 1] : 0u) + inc - myc;
    unsigned tot = sh->wS[7];
    unsigned preP = exc & 0xffffu, preY = exc >> 16;
    unsigned totP = tot & 0xffffu, totY = tot >> 16;
    if (tid == 0) {
        sh->sBP = atomicAdd(&g_ccnt[2 * img], totP);
        sh->sBY = atomicAdd(&g_ccnt[2 * img + 1], totY);
        if (ovf) { g_flag[2 * img] = 1; g_flag[2 * img + 1] = 1; }
    }
    __syncthreads();
    float* candP = g_cand[2 * img];
    float* candY = g_cand[2 * img + 1];
    for (unsigned k = 0; k < nP; k++) { unsigned o = sh->sBP + preP + k; if (o < CAP) candP[o] = myP[k]; }
    for (unsigned k = 0; k < nY; k++) { unsigned o = sh->sBY + preY + k; if (o < CAP) candY[o] = myY[k]; }
}
__global__ void __launch_bounds__(256) k_scan(const float* P, const float* Y, const void* M) {
    __shared__ ScanShared sh;    // single instance shared across instantiations
    int m = g_mmode;
    if (m == 0) scan_impl<0>(P, Y, M, &sh);
    else if (m == 2) scan_impl<2>(P, Y, M, &sh);
    else scan_impl<1>(P, Y, M, &sh);
}

// select (+ inline exact fallback). 128 blocks.
__global__ void __launch_bounds__(256) k_select(const float* P, const float* Y, const void* M) {
    __shared__ double redD[8];
    __shared__ unsigned long long redU[8];
    __shared__ int sFB;
    int t = blockIdx.x, img = t >> 1, tid = threadIdx.x;
    unsigned cnt = g_cnt[img];
    if (cnt == 0) { if (tid == 0) { g_med[t] = 0.f; g_isc[t] = (float)(1.0 / EPSV); } return; }
    unsigned r = (cnt - 1) >> 1;
    if (tid == 0) {
        int fb = g_flag[t];
        if (!fb) {
            unsigned nb_lo = g_nb[t];
            unsigned ncand = g_ccnt[t];
            long long j = (long long)r - (long long)nb_lo;
            if (ncand > CAP || j < 0 || j >= (long long)ncand) fb = 1;
        }
        sFB = fb;
    }
    __syncthreads();
    if (!sFB) {
        unsigned nb_lo = g_nb[t];
        unsigned ncand = g_ccnt[t];
        unsigned j = r - nb_lo;
        unsigned mkey = radixSelectG(g_cand[t], (int)ncand, j);
        unsigned nl = 0;
        double sl = 0;
        for (int i = tid; i < (int)ncand; i += 256) {
            float v = g_cand[t][i];
            if (monot(v) < mkey) { nl++; sl += (double)v; }
        }
        double sls = blockReduceD<256>(sl, redD);
        __syncthreads();
        unsigned long long nls = blockReduceU<256>(nl, redU);
        if (tid == 0) {
            double med = (double)inv_monot(mkey);
            double nb = (double)nb_lo + (double)nls;
            double Sb = g_sb[t] + sls;
            double abs_sum = g_stot[t] - 2.0 * Sb + med * (2.0 * nb - (double)cnt);
            if (abs_sum < 0.0) abs_sum = 0.0;
            double sc = abs_sum / (double)cnt + EPSV;
            g_med[t] = (float)med;
            g_isc[t] = (float)(1.0 / sc);
        }
        return;
    }
    // exact fallback: masked radix select + one stats pass
    int mode = g_mmode;
    const float* src = (t & 1) ? Y : P;
    int base = img * HWSZ;
    unsigned mkey = radixSelectMaskedG(src, M, base, mode, r);
    unsigned nb = 0;
    double Sb = 0;
    for (int i = tid; i < HWSZ; i += 256) {
        if (!maskRT(M, base + i, mode)) continue;
        float v = src[base + i];
        if (monot(v) < mkey) { nb++; Sb += (double)v; }
    }
    double sbs = blockReduceD<256>(Sb, redD);
    __syncthreads();
    unsigned long long nbs = blockReduceU<256>(nb, redU);
    if (tid == 0) {
        double med = (double)inv_monot(mkey);
        double abs_sum = g_stot[t] - 2.0 * sbs + med * (2.0 * (double)nbs - (double)cnt);
        if (abs_sum < 0.0) abs_sum = 0.0;
        double sc = abs_sum / (double)cnt + EPSV;
        g_med[t] = (float)med;
        g_isc[t] = (float)(1.0 / sc);
    }
}

struct __align__(16) MainShared {
    float sd[15 * ROWP];
    unsigned char sm[15 * ROWP];
    double redD[16];
    unsigned long long redU[16];
};

template <int MODE>
__device__ __forceinline__ void main_impl(const float* P, const float* Y, const void* M, MainShared* sh) {
    float* sd = sh->sd;
    unsigned char* sm = sh->sm;
    int tid = threadIdx.x;
    const float2* P2 = (const float2*)P;
    const float2* Y2 = (const float2*)Y;
    for (int t = blockIdx.x; t < NTILES; t += MAINGRID) {   // exactly 4 uniform iterations
        int img = t / NBANDS;
        int band = t - img * NBANDS;
        bool last = (band == NBANDS - 1);
        int nrows = last ? 14 : 15;
        float medp = g_med[2 * img], medy = g_med[2 * img + 1];
        float iscp = g_isc[2 * img], iscy = g_isc[2 * img + 1];
        int ebase = img * HWSZ + band * BANDSZ;
        int base2 = ebase >> 1;
        for (int f = tid; f < nrows * 259; f += 512) {
            int r = f / 259, j = f - 259 * r;
            int g2 = base2 + r * 259 + j;
            float2 p = P2[g2], q = Y2[g2];
            bool m0, m1;
            loadMask2<MODE>(M, g2, m0, m1);
            int o = r * ROWP + 2 * j;
            float2 dv;
            dv.x = (p.x - medp) * iscp - (q.x - medy) * iscy;
            dv.y = (p.y - medp) * iscp - (q.y - medy) * iscy;
            *(float2*)(sd + o) = dv;
            uchar2 mm; mm.x = m0 ? 1 : 0; mm.y = m1 ? 1 : 0;
            *(uchar2*)(sm + o) = mm;
        }
        if (tid < 15) {
            int o = tid * ROWP + 518;
            sd[o] = 0.f; sd[o + 1] = 0.f; sm[o] = 0; sm[o + 1] = 0;
        }
        if (last) {
            for (int z = tid; z < ROWP; z += 512) { sd[14 * ROWP + z] = 0.f; sm[14 * ROWP + z] = 0; }
        }
        __syncthreads();
        float rho = 0.f, gx = 0.f, gy = 0.f;
        unsigned cx = 0, cy = 0;
        int nprow = last ? 13 : 14;
        for (int g = tid; g < 14 * 130; g += 512) {
            int row = g / 130, gi = g - 130 * row;
            int b = row * ROWP + 4 * gi;
            float4 a = *(const float4*)(sd + b);
            float a4 = sd[b + 4];
            uchar4 mk = *(const uchar4*)(sm + b);
            unsigned char mk4 = sm[b + 4];
            if (mk.x) rho += fabsf(a.x);
            if (mk.y) rho += fabsf(a.y);
            if (mk.z) rho += fabsf(a.z);
            if (mk.w) rho += fabsf(a.w);
            if (mk.x && mk.y) { gx += fabsf(a.y - a.x); cx++; }
            if (mk.y && mk.z) { gx += fabsf(a.z - a.y); cx++; }
            if (mk.z && mk.w) { gx += fabsf(a.w - a.z); cx++; }
            if (mk.w && mk4)  { gx += fabsf(a4 - a.w); cx++; }
            if (row < nprow) {
                float4 c = *(const float4*)(sd + b + ROWP);
                uchar4 mc = *(const uchar4*)(sm + b + ROWP);
                if (mk.x && mc.x) { gy += fabsf(c.x - a.x); cy++; }
                if (mk.y && mc.y) { gy += fabsf(c.y - a.y); cy++; }
                if (mk.z && mc.z) { gy += fabsf(c.z - a.z); cy++; }
                if (mk.w && mc.w) { gy += fabsf(c.w - a.w); cy++; }
            }
        }
        float* d1 = d1buf + img * L1SZ + band * 7 * L1W;
        unsigned char* m1 = m1buf + img * L1SZ + band * 7 * L1W;
        for (int pi = tid; pi < 7 * L1W; pi += 512) {
            int pr = pi / L1W, pc = pi - pr * L1W;
            int o0 = (2 * pr) * ROWP + 2 * pc;
            float2 tp = *(const float2*)(sd + o0);
            float2 bt = *(const float2*)(sd + o0 + ROWP);
            uchar2 mt = *(const uchar2*)(sm + o0);
            uchar2 mb = *(const uchar2*)(sm + o0 + ROWP);
            d1[pi] = 0.25f * ((tp.x + tp.y) + (bt.x + bt.y));
            m1[pi] = (unsigned char)(mt.x | mt.y | mb.x | mb.y);
        }
        double r1 = blockReduceD<512>((double)rho, sh->redD); __syncthreads();
        double r2 = blockReduceD<512>((double)gx, sh->redD);  __syncthreads();
        double r3 = blockReduceD<512>((double)gy, sh->redD);  __syncthreads();
        unsigned long long u1 = blockReduceU<512>(cx, sh->redU); __syncthreads();
        unsigned long long u2 = blockReduceU<512>(cy, sh->redU);
        if (tid == 0) {
            atomicAdd(&g_rho[img], r1);
            atomicAdd(&g_gx[0], r2); atomicAdd(&g_gy[0], r3);
            atomicAdd(&g_cx[0], u1); atomicAdd(&g_cy[0], u2);
        }
        __syncthreads();   // orders smem reuse for next tile
    }
}
__global__ void __launch_bounds__(512) k_main(const float* P, const float* Y, const void* M) {
    __shared__ MainShared sh;    // single instance shared across instantiations
    int m = g_mmode;
    if (m == 0) main_impl<0>(P, Y, M, &sh);
    else if (m == 2) main_impl<2>(P, Y, M, &sh);
    else main_impl<1>(P, Y, M, &sh);
}

// grad level 1 + pool L1 -> L2 (global). 1024 blocks.
__global__ void __launch_bounds__(256) k_gp1() {
    const float* d = d1buf;
    const unsigned char* m = m1buf;
    float* dout = d2buf;
    unsigned char* mo = m2buf;
    __shared__ double redD[8];
    __shared__ unsigned long long redU[8];
    constexpr int per = 259 * 259;
    constexpr int total = NIMG * per;
    float gx = 0.f, gy = 0.f;
    unsigned cx = 0, cy = 0;
    for (int i = blockIdx.x * blockDim.x + threadIdx.x; i < total; i += gridDim.x * blockDim.x) {
        if (!m[i]) continue;
        int rem = i % per;
        int r = rem / 259, c = rem - r * 259;
        float dv = d[i];
        if (c < 258 && m[i + 1]) { gx += fabsf(d[i + 1] - dv); cx++; }
        if (r < 258 && m[i + 259]) { gy += fabsf(d[i + 259] - dv); cy++; }
    }
    constexpr int perO = 129 * 129;
    constexpr int totalO = NIMG * perO;
    for (int i = blockIdx.x * blockDim.x + threadIdx.x; i < totalO; i += gridDim.x * blockDim.x) {
        int img = i / perO, rem = i - img * perO;
        int r = rem / 129, c = rem - r * 129;
        int bi = img * per + (2 * r) * 259 + 2 * c;
        dout[i] = 0.25f * (d[bi] + d[bi + 1] + d[bi + 259] + d[bi + 260]);
        mo[i] = m[bi] | m[bi + 1] | m[bi + 259] | m[bi + 260];
    }
    double r2 = blockReduceD<256>((double)gx, redD); __syncthreads();
    double r3 = blockReduceD<256>((double)gy, redD); __syncthreads();
    unsigned long long u1 = blockReduceU<256>(cx, redU); __syncthreads();
    unsigned long long u2 = blockReduceU<256>(cy, redU);
    if (threadIdx.x == 0) {
        atomicAdd(&g_gx[1], r2); atomicAdd(&g_gy[1], r3);
        atomicAdd(&g_cx[1], u1); atomicAdd(&g_cy[1], u2);
    }
}

// fused tail2: grad L2 (gmem, L2-hot) + pool L2->L3 (smem) + grad L3 (smem). 64 blocks.
__global__ void __launch_bounds__(512) k_tail2() {
    __shared__ float d3s[64 * 64];
    __shared__ unsigned char m3s[64 * 64];
    __shared__ double redD[16];
    __shared__ unsigned long long redU[16];
    int img = blockIdx.x, tid = threadIdx.x;
    const float* d2 = d2buf + img * 129 * 129;
    const unsigned char* m2 = m2buf + img * 129 * 129;
    float gx2 = 0.f, gy2 = 0.f;
    unsigned cx2 = 0, cy2 = 0;
    for (int i = tid; i < 129 * 129; i += 512) {
        if (!m2[i]) continue;
        int r = i / 129, c = i - 129 * r;
        float dv = d2[i];
        if (c < 128 && m2[i + 1]) { gx2 += fabsf(d2[i + 1] - dv); cx2++; }
        if (r < 128 && m2[i + 129]) { gy2 += fabsf(d2[i + 129] - dv); cy2++; }
    }
    for (int i = tid; i < 64 * 64; i += 512) {
        int r = i >> 6, c = i & 63;
        int bi = 2 * r * 129 + 2 * c;
        d3s[i] = 0.25f * (d2[bi] + d2[bi + 1] + d2[bi + 129] + d2[bi + 130]);
        m3s[i] = (unsigned char)(m2[bi] | m2[bi + 1] | m2[bi + 129] | m2[bi + 130]);
    }
    __syncthreads();
    float gx3 = 0.f, gy3 = 0.f;
    unsigned cx3 = 0, cy3 = 0;
    for (int i = tid; i < 64 * 64; i += 512) {
        if (!m3s[i]) continue;
        int r = i >> 6, c = i & 63;
        float dv = d3s[i];
        if (c < 63 && m3s[i + 1]) { gx3 += fabsf(d3s[i + 1] - dv); cx3++; }
        if (r < 63 && m3s[i + 64]) { gy3 += fabsf(d3s[i + 64] - dv); cy3++; }
    }
    __syncthreads();
    double v;
    v = blockReduceD<512>((double)gx2, redD); if (tid == 0) atomicAdd(&g_gx[2], v); __syncthreads();
    v = blockReduceD<512>((double)gy2, redD); if (tid == 0) atomicAdd(&g_gy[2], v); __syncthreads();
    v = blockReduceD<512>((double)gx3, redD); if (tid == 0) atomicAdd(&g_gx[3], v); __syncthreads();
    v = blockReduceD<512>((double)gy3, redD); if (tid == 0) atomicAdd(&g_gy[3], v); __syncthreads();
    unsigned long long u;
    u = blockReduceU<512>(cx2, redU); if (tid == 0) atomicAdd(&g_cx[2], u); __syncthreads();
    u = blockReduceU<512>(cy2, redU); if (tid == 0) atomicAdd(&g_cy[2], u); __syncthreads();
    u = blockReduceU<512>(cx3, redU); if (tid == 0) atomicAdd(&g_cx[3], u); __syncthreads();
    u = blockReduceU<512>(cy3, redU); if (tid == 0) atomicAdd(&g_cy[3], u);
}

__global__ void k_final(float* out) {
    if (threadIdx.x == 0 && blockIdx.x == 0) {
        double ssi = 0;
        for (int i = 0; i < NIMG; i++) {
            double v = (double)g_cnt[i];
            if (v < 1.0) v = 1.0;
            ssi += g_rho[i] / v;
        }
        ssi /= (double)NIMG;
        double g = 0;
        for (int s = 0; s < 4; s++) {
            double cx = (double)g_cx[s]; if (cx < 1.0) cx = 1.0;
            double cy = (double)g_cy[s]; if (cy < 1.0) cy = 1.0;
            g += g_gx[s] / cx + g_gy[s] / cy;
        }
        out[0] = (float)(ssi + 0.5 * (g / 4.0));
    }
}

extern "C" void kernel_launch(void* const* d_in, const int* in_sizes, int n_in,
                              void* d_out, int out_size) {
    const float* pred = (const float*)d_in[0];
    const float* yv = (const float*)d_in[1];
    const void* mask = d_in[2];
    float* out = (float*)d_out;

    k_prep<<<128, 256>>>(pred, yv, mask);
    k_scan<<<dim3(32, NIMG), 256>>>(pred, yv, mask);
    k_select<<<128, 256>>>(pred, yv, mask);
    k_main<<<MAINGRID, 512>>>(pred, yv, mask);
    k_gp1<<<1024, 256>>>();
    k_tail2<<<64, 512>>>();
    k_final<<<1, 32>>>(out);
}

// round 13
// speedup vs baseline: 1.5677x; 1.1007x over previous
#include <cuda_runtime.h>
#include <cstdint>

#define HWSZ 268324
#define HW4  67081
#define WD 518
#define ROWP 520
#define NIMG 64
#define CAP 32768
#define SLOTS 12
#define EPSV 1e-8
#define SAMPN 8192
#define SSTRIDE 8385
#define BANDSZ 7252        // 14 rows * 518
#define NBANDS 37
#define NTILES (NBANDS * NIMG)   // 2368
#define MAINGRID 592             // 2368 / 4
#define L1W 259
#define L1SZ (259*259)
#define G8 33540           // full 8-element groups per image

// ---------------- static device scratch ----------------
__device__ int g_mmode;
__device__ float g_vlo[128], g_vhi[128];
__device__ int g_flag[128];
__device__ unsigned g_cnt[NIMG];
__device__ unsigned g_nb[128];
__device__ double g_sb[128];
__device__ double g_stot[128];
__device__ unsigned g_ccnt[128];
__device__ float g_cand[128][CAP];
__device__ float g_med[128], g_isc[128];
__device__ double g_rho[NIMG];
__device__ double g_gx[4], g_gy[4];
__device__ unsigned long long g_cx[4], g_cy[4];

// +512 element padding: grad kernels read m[i+W]/d[i+W] unconditionally.
__device__ float d1buf[NIMG * L1SZ + 512];
__device__ unsigned char m1buf[NIMG * L1SZ + 512];
__device__ float d2buf[NIMG * 129 * 129 + 512];
__device__ unsigned char m2buf[NIMG * 129 * 129 + 512];
__device__ float d3buf[NIMG * 64 * 64 + 512];
__device__ unsigned char m3buf[NIMG * 64 * 64 + 512];

// ---------------- helpers ----------------
__device__ __forceinline__ unsigned monot(float x) {
    unsigned u = __float_as_uint(x);
    return (u >> 31) ? ~u : (u | 0x80000000u);
}
__device__ __forceinline__ float inv_monot(unsigned k) {
    unsigned u = (k >> 31) ? (k & 0x7FFFFFFFu) : ~k;
    return __uint_as_float(u);
}
__device__ __forceinline__ bool maskRT(const void* m, int i, int mode) {
    return (mode == 0) ? ((const unsigned char*)m)[i] != 0
         : (mode == 2) ? ((const int*)m)[i] != 0
         : ((const float*)m)[i] != 0.f;
}

template <int MODE>
__device__ __forceinline__ bool maskAt(const void* m, int i) {
    if (MODE == 0) return ((const unsigned char*)m)[i] != 0;
    if (MODE == 2) return ((const int*)m)[i] != 0;
    return ((const float*)m)[i] != 0.f;
}
template <int MODE>
__device__ __forceinline__ void loadMask4(const void* m, int g4, bool& b0, bool& b1, bool& b2, bool& b3) {
    if (MODE == 0) { uchar4 v = ((const uchar4*)m)[g4]; b0 = v.x; b1 = v.y; b2 = v.z; b3 = v.w; }
    else if (MODE == 2) { int4 v = ((const int4*)m)[g4]; b0 = v.x != 0; b1 = v.y != 0; b2 = v.z != 0; b3 = v.w != 0; }
    else { float4 v = ((const float4*)m)[g4]; b0 = v.x != 0.f; b1 = v.y != 0.f; b2 = v.z != 0.f; b3 = v.w != 0.f; }
}
template <int MODE>
__device__ __forceinline__ void loadMask2(const void* m, int g2, bool& b0, bool& b1) {
    if (MODE == 0) { uchar2 v = ((const uchar2*)m)[g2]; b0 = v.x; b1 = v.y; }
    else if (MODE == 2) { int2 v = ((const int2*)m)[g2]; b0 = v.x != 0; b1 = v.y != 0; }
    else { float2 v = ((const float2*)m)[g2]; b0 = v.x != 0.f; b1 = v.y != 0.f; }
}

template <int NT>
__device__ __forceinline__ double blockReduceD(double v, double* sh) {
    constexpr int NW = NT / 32;
    for (int o = 16; o; o >>= 1) v += __shfl_down_sync(0xffffffffu, v, o);
    int w = threadIdx.x >> 5, l = threadIdx.x & 31;
    if (l == 0) sh[w] = v;
    __syncthreads();
    double r = 0;
    if (threadIdx.x < NW) {
        r = sh[threadIdx.x];
        for (int o = NW / 2; o; o >>= 1) r += __shfl_down_sync((unsigned)((1ull << NW) - 1), r, o);
    }
    return r;
}
template <int NT>
__device__ __forceinline__ unsigned long long blockReduceU(unsigned long long v, unsigned long long* sh) {
    constexpr int NW = NT / 32;
    for (int o = 16; o; o >>= 1) v += __shfl_down_sync(0xffffffffu, v, o);
    int w = threadIdx.x >> 5, l = threadIdx.x & 31;
    if (l == 0) sh[w] = v;
    __syncthreads();
    unsigned long long r = 0;
    if (threadIdx.x < NW) {
        r = sh[threadIdx.x];
        for (int o = NW / 2; o; o >>= 1) r += __shfl_down_sync((unsigned)((1ull << NW) - 1), r, o);
    }
    return r;
}

// 4-bit radix select over smem monot keys, stopping at STOPSHIFT (coarse bucket).
template <int STOPSHIFT>
__device__ unsigned radixSelectKeysSm(const unsigned* keys, int n, unsigned rank) {
    __shared__ unsigned cnts[8][16];
    __shared__ unsigned sPrefix, sRank;
    int tid = threadIdx.x, w = tid >> 5;
    if (tid == 0) { sPrefix = 0u; sRank = rank; }
    for (int shift = 28; shift >= STOPSHIFT; shift -= 4) {
        if (tid < 128) ((unsigned*)cnts)[tid] = 0u;
        __syncthreads();
        unsigned prefix = sPrefix;
        unsigned hiMask = (shift == 28) ? 0u : (0xFFFFFFFFu << (shift + 4));
        for (int i = tid; i < n; i += 256) {
            unsigned k = keys[i];
            if ((k & hiMask) == prefix) atomicAdd(&cnts[w][(k >> shift) & 15], 1u);
        }
        __syncthreads();
        if (tid == 0) {
            unsigned r = sRank, cum = 0;
            for (int d = 0; d < 16; d++) {
                unsigned c = 0;
                for (int ww = 0; ww < 8; ww++) c += cnts[ww][d];
                if (cum + c > r) { sPrefix = prefix | ((unsigned)d << shift); sRank = r - cum; break; }
                cum += c;
            }
        }
        __syncthreads();
    }
    return sPrefix;
}

// full 8-pass select over global float array (256 threads)
__device__ unsigned radixSelectG(const float* vals, int n, unsigned rank) {
    __shared__ unsigned cnts[8][16];
    __shared__ unsigned sPrefix, sRank;
    int tid = threadIdx.x, w = tid >> 5;
    if (tid == 0) { sPrefix = 0u; sRank = rank; }
    for (int shift = 28; shift >= 0; shift -= 4) {
        if (tid < 128) ((unsigned*)cnts)[tid] = 0u;
        __syncthreads();
        unsigned prefix = sPrefix;
        unsigned hiMask = (shift == 28) ? 0u : (0xFFFFFFFFu << (shift + 4));
        for (int i = tid; i < n; i += 256) {
            unsigned k = monot(vals[i]);
            if ((k & hiMask) == prefix) atomicAdd(&cnts[w][(k >> shift) & 15], 1u);
        }
        __syncthreads();
        if (tid == 0) {
            unsigned r = sRank, cum = 0;
            for (int d = 0; d < 16; d++) {
                unsigned c = 0;
                for (int ww = 0; ww < 8; ww++) c += cnts[ww][d];
                if (cum + c > r) { sPrefix = prefix | ((unsigned)d << shift); sRank = r - cum; break; }
                cum += c;
            }
        }
        __syncthreads();
    }
    return sPrefix;
}

// masked radix select over one image of a global tensor (256 threads; fallback path)
__device__ unsigned radixSelectMaskedG(const float* src, const void* M, int base, int mode, unsigned rank) {
    __shared__ unsigned cnts[8][16];
    __shared__ unsigned sPrefix, sRank;
    int tid = threadIdx.x, w = tid >> 5;
    if (tid == 0) { sPrefix = 0u; sRank = rank; }
    for (int shift = 28; shift >= 0; shift -= 4) {
        if (tid < 128) ((unsigned*)cnts)[tid] = 0u;
        __syncthreads();
        unsigned prefix = sPrefix;
        unsigned hiMask = (shift == 28) ? 0u : (0xFFFFFFFFu << (shift + 4));
        for (int i = tid; i < HWSZ; i += 256) {
            if (!maskRT(M, base + i, mode)) continue;
            unsigned k = monot(src[base + i]);
            if ((k & hiMask) == prefix) atomicAdd(&cnts[w][(k >> shift) & 15], 1u);
        }
        __syncthreads();
        if (tid == 0) {
            unsigned r = sRank, cum = 0;
            for (int d = 0; d < 16; d++) {
                unsigned c = 0;
                for (int ww = 0; ww < 8; ww++) c += cnts[ww][d];
                if (cum + c > r) { sPrefix = prefix | ((unsigned)d << shift); sRank = r - cum; break; }
                cum += c;
            }
        }
        __syncthreads();
    }
    return sPrefix;
}

// ---------------- kernels ----------------
// k_prep: init globals + per-(img,tensor) sampling + coarse quantile window. 128 blocks.
__global__ void __launch_bounds__(256) k_prep(const float* P, const float* Y, const void* M) {
    __shared__ unsigned skeys[SAMPN];
    __shared__ unsigned sN;
    __shared__ int sMode;
    int t = blockIdx.x, img = t >> 1, tid = threadIdx.x;
    if (tid == 0) {
        const unsigned char* b = (const unsigned char*)M;
        bool nonbin = false, offnz = false;
        for (int j = 0; j < 256; j++) {
            unsigned char v = b[j];
            if (v > 1) nonbin = true;
            if ((j & 3) && v) offnz = true;
        }
        int mode = nonbin ? 1 : (offnz ? 0 : 2);
        sMode = mode;
        if (t == 0) g_mmode = mode;
        sN = 0u;
    }
    if (tid == 1) { g_nb[t] = 0u; g_sb[t] = 0.0; g_stot[t] = 0.0; g_ccnt[t] = 0u; g_flag[t] = 0; }
    if (tid == 2 && (t & 1) == 0) { g_cnt[img] = 0u; g_rho[img] = 0.0; }
    if (t == 0 && tid >= 8 && tid < 12) {
        int s = tid - 8;
        g_gx[s] = 0.0; g_gy[s] = 0.0; g_cx[s] = 0ull; g_cy[s] = 0ull;
    }
    __syncthreads();
    int mode = sMode;
    const float* src = (t & 1) ? Y : P;
    int base = img * HWSZ;
    for (int bt = 0; bt < 8; bt++) {
        float xv[4]; bool mv[4];
#pragma unroll
        for (int k = 0; k < 4; k++) {
            int idx = base + (bt * 4 + k) * SSTRIDE + tid;
            xv[k] = src[idx];
            mv[k] = maskRT(M, idx, mode);
        }
#pragma unroll
        for (int k = 0; k < 4; k++) {
            unsigned bal = __ballot_sync(0xffffffffu, mv[k]);
            if (bal) {
                int lane = tid & 31;
                unsigned pos = 0;
                int leader = __ffs(bal) - 1;
                if (lane == leader) pos = atomicAdd(&sN, (unsigned)__popc(bal));
                pos = __shfl_sync(0xffffffffu, pos, leader);
                if (mv[k]) skeys[pos + __popc(bal & ((1u << lane) - 1))] = monot(xv[k]);
            }
        }
    }
    __syncthreads();
    int n = (int)sN;
    if (n == 0) {
        if (tid == 0) { g_vlo[t] = __int_as_float(0x7f800000); g_vhi[t] = __int_as_float(0xff800000); }
        return;
    }
    unsigned rlo = (unsigned)(((long long)(n - 1) * 475) / 1000);
    unsigned rhi = (unsigned)((((long long)(n - 1) * 525) + 999) / 1000);
    if (rhi > (unsigned)(n - 1)) rhi = (unsigned)(n - 1);
    unsigned klo = radixSelectKeysSm<16>(skeys, n, rlo);
    unsigned khi = radixSelectKeysSm<16>(skeys, n, rhi) | 0xFFFFu;
    if (tid == 0) { g_vlo[t] = inv_monot(klo); g_vhi[t] = inv_monot(khi); }
}

struct ScanShared {
    float slotP[256 * SLOTS];
    float slotY[256 * SLOTS];
    unsigned wS[8];
    unsigned sBP, sBY;
    double redD[8];
    unsigned long long redU[8];
};

template <int MODE>
__device__ __forceinline__ void scan_impl(const float* P, const float* Y, const void* M, ScanShared* sh) {
    int img = blockIdx.y, bx = blockIdx.x, tid = threadIdx.x;
    int s = (bx * G8) >> 5;
    int e = ((bx + 1) * G8) >> 5;
    int iters = ((e - s) + 255) >> 8;
    float vloP = g_vlo[2 * img], vhiP = g_vhi[2 * img];
    float vloY = g_vlo[2 * img + 1], vhiY = g_vhi[2 * img + 1];
    const float4* P4 = (const float4*)P;
    const float4* Y4 = (const float4*)Y;
    float* myP = sh->slotP + tid * SLOTS;
    float* myY = sh->slotY + tid * SLOTS;
    unsigned cnt = 0, nbP = 0, nbY = 0, mcP = 0, mcY = 0;
    float sbP = 0.f, sbY = 0.f, stP = 0.f, stY = 0.f;
    for (int it = 0; it < iters; it++) {
        int g = s + it * 256 + tid;
        bool ok = g < e;
        int idx4 = img * HW4 + 2 * (ok ? g : s);
        float4 p0 = P4[idx4], p1 = P4[idx4 + 1];
        float4 q0 = Y4[idx4], q1 = Y4[idx4 + 1];
        float pv[8] = {p0.x, p0.y, p0.z, p0.w, p1.x, p1.y, p1.z, p1.w};
        float qv[8] = {q0.x, q0.y, q0.z, q0.w, q1.x, q1.y, q1.z, q1.w};
        bool mv[8];
        if (MODE == 0) {
            const unsigned* Mu = (const unsigned*)M;
            unsigned ma = Mu[idx4], mb = Mu[idx4 + 1];
#pragma unroll
            for (int j = 0; j < 4; j++) { mv[j] = (ma >> (8 * j)) & 0xffu; mv[4 + j] = (mb >> (8 * j)) & 0xffu; }
        } else {
            loadMask4<MODE>(M, idx4, mv[0], mv[1], mv[2], mv[3]);
            loadMask4<MODE>(M, idx4 + 1, mv[4], mv[5], mv[6], mv[7]);
        }
#pragma unroll
        for (int j = 0; j < 8; j++) {
            if (ok && mv[j]) {
                cnt++;
                float a = pv[j];
                stP += a;
                if (a < vloP) { nbP++; sbP += a; }
                else if (a <= vhiP) { if (mcP < SLOTS) myP[mcP] = a; mcP++; }
                float b = qv[j];
                stY += b;
                if (b < vloY) { nbY++; sbY += b; }
                else if (b <= vhiY) { if (mcY < SLOTS) myY[mcY] = b; mcY++; }
            }
        }
    }
    if (bx == 31 && tid < 4) {
        int ei = img * HWSZ + G8 * 8 + tid;
        if (maskAt<MODE>(M, ei)) {
            cnt++;
            float a = P[ei];
            stP += a;
            if (a < vloP) { nbP++; sbP += a; }
            else if (a <= vhiP) { if (mcP < SLOTS) myP[mcP] = a; mcP++; }
            float b = Y[ei];
            stY += b;
            if (b < vloY) { nbY++; sbY += b; }
            else if (b <= vhiY) { if (mcY < SLOTS) myY[mcY] = b; mcY++; }
        }
    }
    int ovf = __syncthreads_or((mcP > SLOTS) | (mcY > SLOTS));
    unsigned nP = min(mcP, (unsigned)SLOTS), nY = min(mcY, (unsigned)SLOTS);
    double r;
    r = blockReduceD<256>((double)sbP, sh->redD); if (tid == 0) atomicAdd(&g_sb[2 * img], r); __syncthreads();
    r = blockReduceD<256>((double)sbY, sh->redD); if (tid == 0) atomicAdd(&g_sb[2 * img + 1], r); __syncthreads();
    r = blockReduceD<256>((double)stP, sh->redD); if (tid == 0) atomicAdd(&g_stot[2 * img], r); __syncthreads();
    r = blockReduceD<256>((double)stY, sh->redD); if (tid == 0) atomicAdd(&g_stot[2 * img + 1], r); __syncthreads();
    unsigned long long u;
    u = blockReduceU<256>(cnt, sh->redU); if (tid == 0) atomicAdd(&g_cnt[img], (unsigned)u); __syncthreads();
    u = blockReduceU<256>(nbP, sh->redU); if (tid == 0) atomicAdd(&g_nb[2 * img], (unsigned)u); __syncthreads();
    u = blockReduceU<256>(nbY, sh->redU); if (tid == 0) atomicAdd(&g_nb[2 * img + 1], (unsigned)u);
    __syncthreads();
    int lane = tid & 31, w = tid >> 5;
    unsigned myc = nP | (nY << 16);
    unsigned inc = myc;
    for (int o = 1; o < 32; o <<= 1) {
        unsigned v2 = __shfl_up_sync(0xffffffffu, inc, o);
        if (lane >= o) inc += v2;
    }
    if (lane == 31) sh->wS[w] = inc;
    __syncthreads();
    if (tid < 8) {
        unsigned v2 = sh->wS[tid];
        for (int o = 1; o < 8; o <<= 1) {
            unsigned v3 = __shfl_up_sync(0xffu, v2, o);
            if (tid >= o) v2 += v3;
        }
        sh->wS[tid] = v2;
    }
    __syncthreads();
    unsigned exc = ((w > 0) ? sh->wS[w - 1] : 0u) + inc - myc;
    unsigned tot = sh->wS[7];
    unsigned preP = exc & 0xffffu, preY = exc >> 16;
    unsigned totP = tot & 0xffffu, totY = tot >> 16;
    if (tid == 0) {
        sh->sBP = atomicAdd(&g_ccnt[2 * img], totP);
        sh->sBY = atomicAdd(&g_ccnt[2 * img + 1], totY);
        if (ovf) { g_flag[2 * img] = 1; g_flag[2 * img + 1] = 1; }
    }
    __syncthreads();
    float* candP = g_cand[2 * img];
    float* candY = g_cand[2 * img + 1];
    for (unsigned k = 0; k < nP; k++) { unsigned o = sh->sBP + preP + k; if (o < CAP) candP[o] = myP[k]; }
    for (unsigned k = 0; k < nY; k++) { unsigned o = sh->sBY + preY + k; if (o < CAP) candY[o] = myY[k]; }
}
__global__ void __launch_bounds__(256) k_scan(const float* P, const float* Y, const void* M) {
    __shared__ ScanShared sh;
    int m = g_mmode;
    if (m == 0) scan_impl<0>(P, Y, M, &sh);
    else if (m == 2) scan_impl<2>(P, Y, M, &sh);
    else scan_impl<1>(P, Y, M, &sh);
}

// select (+ inline exact fallback). 128 blocks.
__global__ void __launch_bounds__(256) k_select(const float* P, const float* Y, const void* M) {
    __shared__ double redD[8];
    __shared__ unsigned long long redU[8];
    __shared__ int sFB;
    int t = blockIdx.x, img = t >> 1, tid = threadIdx.x;
    unsigned cnt = g_cnt[img];
    if (cnt == 0) { if (tid == 0) { g_med[t] = 0.f; g_isc[t] = (float)(1.0 / EPSV); } return; }
    unsigned r = (cnt - 1) >> 1;
    if (tid == 0) {
        int fb = g_flag[t];
        if (!fb) {
            unsigned nb_lo = g_nb[t];
            unsigned ncand = g_ccnt[t];
            long long j = (long long)r - (long long)nb_lo;
            if (ncand > CAP || j < 0 || j >= (long long)ncand) fb = 1;
        }
        sFB = fb;
    }
    __syncthreads();
    if (!sFB) {
        unsigned nb_lo = g_nb[t];
        unsigned ncand = g_ccnt[t];
        unsigned j = r - nb_lo;
        unsigned mkey = radixSelectG(g_cand[t], (int)ncand, j);
        unsigned nl = 0;
        double sl = 0;
        for (int i = tid; i < (int)ncand; i += 256) {
            float v = g_cand[t][i];
            if (monot(v) < mkey) { nl++; sl += (double)v; }
        }
        double sls = blockReduceD<256>(sl, redD);
        __syncthreads();
        unsigned long long nls = blockReduceU<256>(nl, redU);
        if (tid == 0) {
            double med = (double)inv_monot(mkey);
            double nb = (double)nb_lo + (double)nls;
            double Sb = g_sb[t] + sls;
            double abs_sum = g_stot[t] - 2.0 * Sb + med * (2.0 * nb - (double)cnt);
            if (abs_sum < 0.0) abs_sum = 0.0;
            double sc = abs_sum / (double)cnt + EPSV;
            g_med[t] = (float)med;
            g_isc[t] = (float)(1.0 / sc);
        }
        return;
    }
    int mode = g_mmode;
    const float* src = (t & 1) ? Y : P;
    int base = img * HWSZ;
    unsigned mkey = radixSelectMaskedG(src, M, base, mode, r);
    unsigned nb = 0;
    double Sb = 0;
    for (int i = tid; i < HWSZ; i += 256) {
        if (!maskRT(M, base + i, mode)) continue;
        float v = src[base + i];
        if (monot(v) < mkey) { nb++; Sb += (double)v; }
    }
    double sbs = blockReduceD<256>(Sb, redD);
    __syncthreads();
    unsigned long long nbs = blockReduceU<256>(nb, redU);
    if (tid == 0) {
        double med = (double)inv_monot(mkey);
        double abs_sum = g_stot[t] - 2.0 * sbs + med * (2.0 * (double)nbs - (double)cnt);
        if (abs_sum < 0.0) abs_sum = 0.0;
        double sc = abs_sum / (double)cnt + EPSV;
        g_med[t] = (float)med;
        g_isc[t] = (float)(1.0 / sc);
    }
}

struct __align__(16) MainShared {
    float sd[15 * ROWP];
    unsigned char sm[15 * ROWP];
    double redD[16];
    unsigned long long redU[16];
};

template <int MODE>
__device__ __forceinline__ void main_impl(const float* P, const float* Y, const void* M, MainShared* sh) {
    float* sd = sh->sd;
    unsigned char* sm = sh->sm;
    int tid = threadIdx.x;
    const float2* P2 = (const float2*)P;
    const float2* Y2 = (const float2*)Y;
    for (int t = blockIdx.x; t < NTILES; t += MAINGRID) {
        int img = t / NBANDS;
        int band = t - img * NBANDS;
        bool last = (band == NBANDS - 1);
        int nrows = last ? 14 : 15;
        float medp = g_med[2 * img], medy = g_med[2 * img + 1];
        float iscp = g_isc[2 * img], iscy = g_isc[2 * img + 1];
        int ebase = img * HWSZ + band * BANDSZ;
        int base2 = ebase >> 1;
        for (int f = tid; f < nrows * 259; f += 512) {
            int r = f / 259, j = f - 259 * r;
            int g2 = base2 + r * 259 + j;
            float2 p = P2[g2], q = Y2[g2];
            bool m0, m1;
            loadMask2<MODE>(M, g2, m0, m1);
            int o = r * ROWP + 2 * j;
            float2 dv;
            dv.x = (p.x - medp) * iscp - (q.x - medy) * iscy;
            dv.y = (p.y - medp) * iscp - (q.y - medy) * iscy;
            *(float2*)(sd + o) = dv;
            uchar2 mm; mm.x = m0 ? 1 : 0; mm.y = m1 ? 1 : 0;
            *(uchar2*)(sm + o) = mm;
        }
        if (tid < 15) {
            int o = tid * ROWP + 518;
            sd[o] = 0.f; sd[o + 1] = 0.f; sm[o] = 0; sm[o + 1] = 0;
        }
        if (last) {
            for (int z = tid; z < ROWP; z += 512) { sd[14 * ROWP + z] = 0.f; sm[14 * ROWP + z] = 0; }
        }
        __syncthreads();
        float rho = 0.f, gx = 0.f, gy = 0.f;
        unsigned cx = 0, cy = 0;
        int nprow = last ? 13 : 14;
        for (int g = tid; g < 14 * 130; g += 512) {
            int row = g / 130, gi = g - 130 * row;
            int b = row * ROWP + 4 * gi;
            float4 a = *(const float4*)(sd + b);
            float a4 = sd[b + 4];
            uchar4 mk = *(const uchar4*)(sm + b);
            unsigned char mk4 = sm[b + 4];
            if (mk.x) rho += fabsf(a.x);
            if (mk.y) rho += fabsf(a.y);
            if (mk.z) rho += fabsf(a.z);
            if (mk.w) rho += fabsf(a.w);
            if (mk.x && mk.y) { gx += fabsf(a.y - a.x); cx++; }
            if (mk.y && mk.z) { gx += fabsf(a.z - a.y); cx++; }
            if (mk.z && mk.w) { gx += fabsf(a.w - a.z); cx++; }
            if (mk.w && mk4)  { gx += fabsf(a4 - a.w); cx++; }
            if (row < nprow) {
                float4 c = *(const float4*)(sd + b + ROWP);
                uchar4 mc = *(const uchar4*)(sm + b + ROWP);
                if (mk.x && mc.x) { gy += fabsf(c.x - a.x); cy++; }
                if (mk.y && mc.y) { gy += fabsf(c.y - a.y); cy++; }
                if (mk.z && mc.z) { gy += fabsf(c.z - a.z); cy++; }
                if (mk.w && mc.w) { gy += fabsf(c.w - a.w); cy++; }
            }
        }
        float* d1 = d1buf + img * L1SZ + band * 7 * L1W;
        unsigned char* m1 = m1buf + img * L1SZ + band * 7 * L1W;
        for (int pi = tid; pi < 7 * L1W; pi += 512) {
            int pr = pi / L1W, pc = pi - pr * L1W;
            int o0 = (2 * pr) * ROWP + 2 * pc;
            float2 tp = *(const float2*)(sd + o0);
            float2 bt = *(const float2*)(sd + o0 + ROWP);
            uchar2 mt = *(const uchar2*)(sm + o0);
            uchar2 mb = *(const uchar2*)(sm + o0 + ROWP);
            d1[pi] = 0.25f * ((tp.x + tp.y) + (bt.x + bt.y));
            m1[pi] = (unsigned char)(mt.x | mt.y | mb.x | mb.y);
        }
        double r1 = blockReduceD<512>((double)rho, sh->redD); __syncthreads();
        double r2 = blockReduceD<512>((double)gx, sh->redD);  __syncthreads();
        double r3 = blockReduceD<512>((double)gy, sh->redD);  __syncthreads();
        unsigned long long u1 = blockReduceU<512>(cx, sh->redU); __syncthreads();
        unsigned long long u2 = blockReduceU<512>(cy, sh->redU);
        if (tid == 0) {
            atomicAdd(&g_rho[img], r1);
            atomicAdd(&g_gx[0], r2); atomicAdd(&g_gy[0], r3);
            atomicAdd(&g_cx[0], u1); atomicAdd(&g_cy[0], u2);
        }
        __syncthreads();
    }
}
__global__ void __launch_bounds__(512) k_main(const float* P, const float* Y, const void* M) {
    __shared__ MainShared sh;
    int m = g_mmode;
    if (m == 0) main_impl<0>(P, Y, M, &sh);
    else if (m == 2) main_impl<2>(P, Y, M, &sh);
    else main_impl<1>(P, Y, M, &sh);
}

// fused grad(level LVL) + pool(LVL -> LVL+1); unconditional loads + predicated accumulate.
template <int LVL, int HC, int WC, int HO, int WO>
__global__ void __launch_bounds__(256) k_gp() {
    const float* d; const unsigned char* m; float* dout; unsigned char* mo;
    if (LVL == 1) { d = d1buf; m = m1buf; dout = d2buf; mo = m2buf; }
    else { d = d2buf; m = m2buf; dout = d3buf; mo = m3buf; }
    __shared__ double redD[8];
    __shared__ unsigned long long redU[8];
    constexpr int per = HC * WC;
    constexpr int total = NIMG * per;
    float gx = 0.f, gy = 0.f;
    unsigned cx = 0, cy = 0;
    for (int i = blockIdx.x * blockDim.x + threadIdx.x; i < total; i += gridDim.x * blockDim.x) {
        // unconditional loads (buffers padded) -> front-batched, MLP high
        unsigned char mc = m[i], mr = m[i + 1], mb = m[i + WC];
        float dv = d[i], dr = d[i + 1], db = d[i + WC];
        int rem = i % per;
        int r = rem / WC, c = rem - r * WC;
        bool okx = mc && mr && (c < WC - 1);
        bool oky = mc && mb && (r < HC - 1);
        if (okx) { gx += fabsf(dr - dv); cx++; }
        if (oky) { gy += fabsf(db - dv); cy++; }
    }
    constexpr int perO = HO * WO;
    constexpr int totalO = NIMG * perO;
    for (int i = blockIdx.x * blockDim.x + threadIdx.x; i < totalO; i += gridDim.x * blockDim.x) {
        int img = i / perO, rem = i - img * perO;
        int r = rem / WO, c = rem - r * WO;
        int bi = img * per + (2 * r) * WC + 2 * c;
        dout[i] = 0.25f * (d[bi] + d[bi + 1] + d[bi + WC] + d[bi + WC + 1]);
        mo[i] = m[bi] | m[bi + 1] | m[bi + WC] | m[bi + WC + 1];
    }
    double r2 = blockReduceD<256>((double)gx, redD); __syncthreads();
    double r3 = blockReduceD<256>((double)gy, redD); __syncthreads();
    unsigned long long u1 = blockReduceU<256>(cx, redU); __syncthreads();
    unsigned long long u2 = blockReduceU<256>(cy, redU);
    if (threadIdx.x == 0) {
        atomicAdd(&g_gx[LVL], r2); atomicAdd(&g_gy[LVL], r3);
        atomicAdd(&g_cx[LVL], u1); atomicAdd(&g_cy[LVL], u2);
    }
}

__global__ void __launch_bounds__(256) k_grad3() {
    const float* d = d3buf;
    const unsigned char* m = m3buf;
    __shared__ double redD[8];
    __shared__ unsigned long long redU[8];
    constexpr int per = 64 * 64;
    constexpr int total = NIMG * per;
    float gx = 0.f, gy = 0.f;
    unsigned cx = 0, cy = 0;
    for (int i = blockIdx.x * blockDim.x + threadIdx.x; i < total; i += gridDim.x * blockDim.x) {
        unsigned char mc = m[i], mr = m[i + 1], mb = m[i + 64];
        float dv = d[i], dr = d[i + 1], db = d[i + 64];
        int rem = i & (per - 1);
        int r = rem >> 6, c = rem & 63;
        bool okx = mc && mr && (c < 63);
        bool oky = mc && mb && (r < 63);
        if (okx) { gx += fabsf(dr - dv); cx++; }
        if (oky) { gy += fabsf(db - dv); cy++; }
    }
    double r2 = blockReduceD<256>((double)gx, redD); __syncthreads();
    double r3 = blockReduceD<256>((double)gy, redD); __syncthreads();
    unsigned long long u1 = blockReduceU<256>(cx, redU); __syncthreads();
    unsigned long long u2 = blockReduceU<256>(cy, redU);
    if (threadIdx.x == 0) {
        atomicAdd(&g_gx[3], r2); atomicAdd(&g_gy[3], r3);
        atomicAdd(&g_cx[3], u1); atomicAdd(&g_cy[3], u2);
    }
}

__global__ void k_final(float* out) {
    if (threadIdx.x == 0 && blockIdx.x == 0) {
        double ssi = 0;
        for (int i = 0; i < NIMG; i++) {
            double v = (double)g_cnt[i];
            if (v < 1.0) v = 1.0;
            ssi += g_rho[i] / v;
        }
        ssi /= (double)NIMG;
        double g = 0;
        for (int s = 0; s < 4; s++) {
            double cx = (double)g_cx[s]; if (cx < 1.0) cx = 1.0;
            double cy = (double)g_cy[s]; if (cy < 1.0) cy = 1.0;
            g += g_gx[s] / cx + g_gy[s] / cy;
        }
        out[0] = (float)(ssi + 0.5 * (g / 4.0));
    }
}

extern "C" void kernel_launch(void* const* d_in, const int* in_sizes, int n_in,
                              void* d_out, int out_size) {
    const float* pred = (const float*)d_in[0];
    const float* yv = (const float*)d_in[1];
    const void* mask = d_in[2];
    float* out = (float*)d_out;

    k_prep<<<128, 256>>>(pred, yv, mask);
    k_scan<<<dim3(32, NIMG), 256>>>(pred, yv, mask);
    k_select<<<128, 256>>>(pred, yv, mask);
    k_main<<<MAINGRID, 512>>>(pred, yv, mask);
    k_gp<1, 259, 259, 129, 129><<<1024, 256>>>();
    k_gp<2, 129, 129, 64, 64><<<512, 256>>>();
    k_grad3<<<256, 256>>>();
    k_final<<<1, 32>>>(out);
}